// round 10
// baseline (speedup 1.0000x reference)
#include <cuda_runtime.h>
#include <cuda_bf16.h>
#include <cstdint>

#define NROWS 200000
#define CIN1  64
#define COUT  128
#define NTAPS 27
#define EPSBN 1e-5f
#define NPART 1563   // ceil(NROWS/128) == conv grid size

// ---------------- scratch (device globals; no allocation allowed) ----------
__device__ float g_hpre[(size_t)NROWS * COUT];    // conv1 pre-BN
__device__ float g_respre[(size_t)NROWS * COUT];  // conv2 pre-BN
__device__ float g_skippre[(size_t)NROWS * COUT]; // skip pre-BN
__device__ __nv_bfloat16 g_fhi[(size_t)NROWS * CIN1];
__device__ __nv_bfloat16 g_flo[(size_t)NROWS * CIN1];
__device__ __nv_bfloat16 g_hhi[(size_t)NROWS * COUT];
__device__ __nv_bfloat16 g_hlo[(size_t)NROWS * COUT];
__device__ __nv_bfloat16 g_w1hi[(size_t)NTAPS * COUT * CIN1];  // [tap][n][k]
__device__ __nv_bfloat16 g_w1lo[(size_t)NTAPS * COUT * CIN1];
__device__ __nv_bfloat16 g_w2hi[(size_t)NTAPS * COUT * COUT];
__device__ __nv_bfloat16 g_w2lo[(size_t)NTAPS * COUT * COUT];
__device__ __nv_bfloat16 g_wskhi[(size_t)COUT * CIN1];
__device__ __nv_bfloat16 g_wsklo[(size_t)COUT * CIN1];
__device__ float g_psum[2][NPART][COUT];   // fused per-CTA stats partials
__device__ float g_psq[2][NPART][COUT];
__device__ float g_inv[3][COUT];    // g * rsqrt(var+eps)
__device__ float g_shift[3][COUT];  // b - mean*inv

// ---------------- PTX helpers (baseline features only) -----------------------
__device__ __forceinline__ uint32_t smem_u32(const void* p) {
    uint32_t a;
    asm("{ .reg .u64 t; cvta.to.shared.u64 t, %1; cvt.u32.u64 %0, t; }"
        : "=r"(a) : "l"(p));
    return a;
}
__device__ __forceinline__ void cpasync16(uint32_t dst, const void* src, int srcsize) {
    asm volatile("cp.async.cg.shared.global [%0], [%1], 16, %2;"
                 :: "r"(dst), "l"(src), "r"(srcsize));
}
__device__ __forceinline__ void cpcommit() {
    asm volatile("cp.async.commit_group;");
}
__device__ __forceinline__ void ldm4(uint32_t* r, uint32_t addr) {
    asm volatile("ldmatrix.sync.aligned.m8n8.x4.shared.b16 {%0,%1,%2,%3}, [%4];"
                 : "=r"(r[0]), "=r"(r[1]), "=r"(r[2]), "=r"(r[3]) : "r"(addr));
}
__device__ __forceinline__ void mma16816(float* d, const uint32_t* a, const uint32_t* b) {
    asm volatile(
        "mma.sync.aligned.m16n8k16.row.col.f32.bf16.bf16.f32 "
        "{%0,%1,%2,%3},{%4,%5,%6,%7},{%8,%9},{%0,%1,%2,%3};"
        : "+f"(d[0]), "+f"(d[1]), "+f"(d[2]), "+f"(d[3])
        : "r"(a[0]), "r"(a[1]), "r"(a[2]), "r"(a[3]), "r"(b[0]), "r"(b[1]));
}

// smem tile geometry: 128 rows x 64B (32 bf16), XOR swizzle, no padding.
// phys_chunk = chunk ^ ((row>>1)&3): conflict-free ldmatrix + compact tiles.
#define TILE_B 8192
#define NSTAGE 3
#define STAGE_B (4 * TILE_B)         // XH, XL, WH, WL = 32 KB
#define XH_OFF 0
#define XL_OFF TILE_B
#define WH_OFF (2 * TILE_B)
#define WL_OFF (3 * TILE_B)

__device__ __forceinline__ uint32_t sw_addr(uint32_t base, int row, int bytecol) {
    const int ch = bytecol >> 4;
    return base + row * 64 + (((uint32_t)(ch ^ ((row >> 1) & 3))) << 4);
}

// ---------------- HMMA gathered multi-tap GEMM -------------------------------
// Y[128-tile, 128] = sum_s gather(X)[128,32] @ W[32,128], split-bf16 3 terms.
// Also emits per-CTA column sum/sumsq partials (fused BN stats).
template <bool GATHER>
__global__ __launch_bounds__(256, 2)
void mma_conv_kernel(const __nv_bfloat16* __restrict__ Xhi,
                     const __nv_bfloat16* __restrict__ Xlo,
                     const int* __restrict__ nbr,
                     const __nv_bfloat16* __restrict__ Whi,
                     const __nv_bfloat16* __restrict__ Wlo,
                     float* __restrict__ Y, int ntaps, int xk, int cptsh,
                     int pslot) {
    extern __shared__ char smem[];
    const uint32_t sb = smem_u32(smem);
    const int tid = threadIdx.x;
    const int wid = tid >> 5;
    const int lid = tid & 31;
    const int row0 = blockIdx.x * 128;
    const int kmask = (1 << cptsh) - 1;
    const int nsub = ntaps << cptsh;

    const int wm = (wid & 1) * 64;      // warp M offset
    const int wn = (wid >> 1) * 32;     // warp N offset

    const int lr = tid >> 1;            // load row 0..127
    const int lc = (tid & 1) * 2;       // chunk pair 0/2

    float acc[4][4][4];
#pragma unroll
    for (int i = 0; i < 4; i++)
#pragma unroll
        for (int j = 0; j < 4; j++)
#pragma unroll
            for (int q = 0; q < 4; q++) acc[i][j][q] = 0.f;

    auto src_of = [&](int s) -> int {
        const int grow = row0 + lr;
        if (!GATHER) return grow;
        const int tap = s >> cptsh;
        return (grow < NROWS) ? __ldg(nbr + (size_t)tap * NROWS + grow) : NROWS;
    };

    auto load_stage = [&](int s, int src) {
        const int buf = s % NSTAGE;
        const int kc = s & kmask;
        const uint32_t st = sb + buf * STAGE_B;
        const bool val = (unsigned)src < (unsigned)NROWS;
        const int srow = val ? src : 0;
        const int sz = val ? 16 : 0;
        const __nv_bfloat16* xh = Xhi + (size_t)srow * xk + kc * 32;
        const __nv_bfloat16* xl = Xlo + (size_t)srow * xk + kc * 32;
        const int tap = s >> cptsh;
        const __nv_bfloat16* wh = Whi + ((size_t)tap * 128 + lr) * xk + kc * 32;
        const __nv_bfloat16* wl = Wlo + ((size_t)tap * 128 + lr) * xk + kc * 32;
        const int sel = (lr >> 1) & 3;
        const uint32_t rbase = st + lr * 64;
#pragma unroll
        for (int c = 0; c < 2; c++) {
            const uint32_t d = rbase + (((uint32_t)((lc + c) ^ sel)) << 4);
            cpasync16(d + XH_OFF, xh + (lc + c) * 8, sz);
            cpasync16(d + XL_OFF, xl + (lc + c) * 8, sz);
            cpasync16(d + WH_OFF, wh + (lc + c) * 8, 16);
            cpasync16(d + WL_OFF, wl + (lc + c) * 8, 16);
        }
    };

    // ---- prologue: 2 stages in flight
    {
        int s0 = src_of(0);
        load_stage(0, s0);
        cpcommit();
    }
    if (nsub > 1) {
        int s1 = src_of(1);
        load_stage(1, s1);
        cpcommit();
    }
    int src2 = (nsub > 2) ? src_of(2) : 0;

    // fragment address lane components
    const int b_nrow = (lid & 7) + ((lid >> 4) << 3);
    const int b_kof = ((lid >> 3) & 1) * 16;
    const int a_row = lid & 15;
    const int a_kof = (lid >> 4) * 16;

    for (int s = 0; s < nsub; s++) {
        if (s + 2 < nsub) {
            load_stage(s + 2, src2);
            cpcommit();
            src2 = src_of(s + 3);   // prefetch gather index 3 stages ahead
            asm volatile("cp.async.wait_group 2;");
        } else if (s + 1 < nsub) {
            asm volatile("cp.async.wait_group 1;");
        } else {
            asm volatile("cp.async.wait_group 0;");
        }
        __syncthreads();

        const uint32_t st = sb + (s % NSTAGE) * STAGE_B;
#pragma unroll
        for (int kh = 0; kh < 2; kh++) {
            const int kb = kh * 32;
            uint32_t bh[4][2], bl[4][2];
#pragma unroll
            for (int half = 0; half < 2; half++) {
                const int r = wn + half * 16 + b_nrow;
                const uint32_t wa = sw_addr(st + WH_OFF, r, kb + b_kof);
                uint32_t rg[4];
                ldm4(rg, wa);
                bh[half * 2][0] = rg[0]; bh[half * 2][1] = rg[1];
                bh[half * 2 + 1][0] = rg[2]; bh[half * 2 + 1][1] = rg[3];
                ldm4(rg, wa + (WL_OFF - WH_OFF));
                bl[half * 2][0] = rg[0]; bl[half * 2][1] = rg[1];
                bl[half * 2 + 1][0] = rg[2]; bl[half * 2 + 1][1] = rg[3];
            }
#pragma unroll
            for (int mi = 0; mi < 4; mi++) {
                const int r = wm + mi * 16 + a_row;
                const uint32_t aa = sw_addr(st + XH_OFF, r, kb + a_kof);
                uint32_t ah[4], al[4];
                ldm4(ah, aa);
                ldm4(al, aa + (XL_OFF - XH_OFF));
#pragma unroll
                for (int ni = 0; ni < 4; ni++) {
                    mma16816(acc[mi][ni], ah, bh[ni]);
                    mma16816(acc[mi][ni], ah, bl[ni]);
                    mma16816(acc[mi][ni], al, bh[ni]);
                }
            }
        }
        __syncthreads();
    }

    // ---- epilogue 1: write fp32 tile
#pragma unroll
    for (int mi = 0; mi < 4; mi++) {
        const int m0 = row0 + wm + mi * 16 + (lid >> 2);
#pragma unroll
        for (int ni = 0; ni < 4; ni++) {
            const int col = wn + ni * 8 + 2 * (lid & 3);
            if (m0 < NROWS)
                *(float2*)(Y + (size_t)m0 * 128 + col) =
                    make_float2(acc[mi][ni][0], acc[mi][ni][1]);
            if (m0 + 8 < NROWS)
                *(float2*)(Y + (size_t)(m0 + 8) * 128 + col) =
                    make_float2(acc[mi][ni][2], acc[mi][ni][3]);
        }
    }

    // ---- epilogue 2: fused column stats (rows beyond NROWS contribute 0)
    float ts[8], tq[8];
#pragma unroll
    for (int ni = 0; ni < 4; ni++)
#pragma unroll
        for (int j = 0; j < 2; j++) {
            float s = 0.f, q = 0.f;
#pragma unroll
            for (int mi = 0; mi < 4; mi++) {
                float v0 = acc[mi][ni][j];
                float v1 = acc[mi][ni][j + 2];
                s += v0 + v1;
                q += v0 * v0 + v1 * v1;
            }
            ts[ni * 2 + j] = s;
            tq[ni * 2 + j] = q;
        }
#pragma unroll
    for (int o = 16; o >= 4; o >>= 1)
#pragma unroll
        for (int i = 0; i < 8; i++) {
            ts[i] += __shfl_down_sync(0xffffffffu, ts[i], o);
            tq[i] += __shfl_down_sync(0xffffffffu, tq[i], o);
        }
    __syncthreads();   // stage smem free for reuse
    float* ss = (float*)smem;          // [8][32]
    float* sq = ss + 256;
    if (lid < 4) {
#pragma unroll
        for (int ni = 0; ni < 4; ni++)
#pragma unroll
            for (int j = 0; j < 2; j++) {
                const int cl = ni * 8 + 2 * lid + j;
                ss[wid * 32 + cl] = ts[ni * 2 + j];
                sq[wid * 32 + cl] = tq[ni * 2 + j];
            }
    }
    __syncthreads();
    if (tid < COUT) {
        const int w0 = (tid >> 5) * 2;
        const int c = tid & 31;
        g_psum[pslot][blockIdx.x][tid] = ss[w0 * 32 + c] + ss[w0 * 32 + 32 + c];
        g_psq[pslot][blockIdx.x][tid]  = sq[w0 * 32 + c] + sq[w0 * 32 + 32 + c];
    }
}

// ---------------- prep: W transpose + bf16 split -----------------------------
__global__ void wsplit_kernel(const float* __restrict__ W,
                              __nv_bfloat16* __restrict__ hi,
                              __nv_bfloat16* __restrict__ lo, int taps, int K) {
    int i = blockIdx.x * blockDim.x + threadIdx.x;
    int total = taps * 128 * K;
    if (i >= total) return;
    int kk = i % K;
    int t2 = i / K;
    int n = t2 & 127;
    int tap = t2 >> 7;
    float v = __ldg(W + ((size_t)tap * K + kk) * 128 + n);
    __nv_bfloat16 h = __float2bfloat16(v);
    hi[i] = h;
    lo[i] = __float2bfloat16(v - __bfloat162float(h));
}

// ---------------- prep: feats bf16 split (vector) ----------------------------
__global__ void xsplit_kernel(const float4* __restrict__ X,
                              uint2* __restrict__ hi, uint2* __restrict__ lo,
                              long long n4) {
    long long i = (long long)blockIdx.x * blockDim.x + threadIdx.x;
    if (i >= n4) return;
    float4 v = X[i];
    __nv_bfloat16 hx = __float2bfloat16(v.x), hy = __float2bfloat16(v.y);
    __nv_bfloat16 hz = __float2bfloat16(v.z), hw = __float2bfloat16(v.w);
    __nv_bfloat162 h01, h23, l01, l23;
    h01.x = hx; h01.y = hy; h23.x = hz; h23.y = hw;
    l01.x = __float2bfloat16(v.x - __bfloat162float(hx));
    l01.y = __float2bfloat16(v.y - __bfloat162float(hy));
    l23.x = __float2bfloat16(v.z - __bfloat162float(hz));
    l23.y = __float2bfloat16(v.w - __bfloat162float(hw));
    hi[i] = make_uint2(*(uint32_t*)&h01, *(uint32_t*)&h23);
    lo[i] = make_uint2(*(uint32_t*)&l01, *(uint32_t*)&l23);
}

// ---------------- BN finalize from fused partials -----------------------------
__global__ void finalize_kernel(const float* __restrict__ g,
                                const float* __restrict__ b, int slot, int pslot) {
    const int col = threadIdx.x;  // 128 threads
    float s0 = 0.f, s1 = 0.f, q0 = 0.f, q1 = 0.f;
    int i = 0;
    for (; i + 1 < NPART; i += 2) {
        s0 += g_psum[pslot][i][col];
        q0 += g_psq[pslot][i][col];
        s1 += g_psum[pslot][i + 1][col];
        q1 += g_psq[pslot][i + 1][col];
    }
    for (; i < NPART; i++) {
        s0 += g_psum[pslot][i][col];
        q0 += g_psq[pslot][i][col];
    }
    float s = s0 + s1, q = q0 + q1;
    float mean = s * (1.0f / NROWS);
    float var = q * (1.0f / NROWS) - mean * mean;
    float inv = g[col] * rsqrtf(var + EPSBN);
    g_inv[slot][col] = inv;
    g_shift[slot][col] = b[col] - mean * inv;
}

// ---------------- BN apply (slot 0) fused with bf16 split --------------------
__global__ void bnsplit_kernel(const float4* __restrict__ X,
                               uint2* __restrict__ hi, uint2* __restrict__ lo) {
    long long i = (long long)blockIdx.x * blockDim.x + threadIdx.x;
    const long long total = (long long)NROWS * COUT / 4;
    if (i >= total) return;
    int c4 = (int)(i & (COUT / 4 - 1)) * 4;
    float4 v = X[i];
    v.x = v.x * g_inv[0][c4 + 0] + g_shift[0][c4 + 0];
    v.y = v.y * g_inv[0][c4 + 1] + g_shift[0][c4 + 1];
    v.z = v.z * g_inv[0][c4 + 2] + g_shift[0][c4 + 2];
    v.w = v.w * g_inv[0][c4 + 3] + g_shift[0][c4 + 3];
    __nv_bfloat16 hx = __float2bfloat16(v.x), hy = __float2bfloat16(v.y);
    __nv_bfloat16 hz = __float2bfloat16(v.z), hw = __float2bfloat16(v.w);
    __nv_bfloat162 h01, h23, l01, l23;
    h01.x = hx; h01.y = hy; h23.x = hz; h23.y = hw;
    l01.x = __float2bfloat16(v.x - __bfloat162float(hx));
    l01.y = __float2bfloat16(v.y - __bfloat162float(hy));
    l23.x = __float2bfloat16(v.z - __bfloat162float(hz));
    l23.y = __float2bfloat16(v.w - __bfloat162float(hw));
    hi[i] = make_uint2(*(uint32_t*)&h01, *(uint32_t*)&h23);
    lo[i] = make_uint2(*(uint32_t*)&l01, *(uint32_t*)&l23);
}

// ---------------- final: relu(bn(res) + bn(skip)) ----------------------------
__global__ void final_kernel(float4* __restrict__ out) {
    long long i = (long long)blockIdx.x * blockDim.x + threadIdx.x;
    const long long total = (long long)NROWS * COUT / 4;
    if (i >= total) return;
    int c4 = (int)(i & (COUT / 4 - 1)) * 4;
    const float4 r = ((const float4*)g_respre)[i];
    const float4 s = ((const float4*)g_skippre)[i];
    float4 o;
    o.x = fmaxf(r.x * g_inv[1][c4 + 0] + g_shift[1][c4 + 0] +
                s.x * g_inv[2][c4 + 0] + g_shift[2][c4 + 0], 0.f);
    o.y = fmaxf(r.y * g_inv[1][c4 + 1] + g_shift[1][c4 + 1] +
                s.y * g_inv[2][c4 + 1] + g_shift[2][c4 + 1], 0.f);
    o.z = fmaxf(r.z * g_inv[1][c4 + 2] + g_shift[1][c4 + 2] +
                s.z * g_inv[2][c4 + 2] + g_shift[2][c4 + 2], 0.f);
    o.w = fmaxf(r.w * g_inv[1][c4 + 3] + g_shift[1][c4 + 3] +
                s.w * g_inv[2][c4 + 3] + g_shift[2][c4 + 3], 0.f);
    out[i] = o;
}

// ---------------- launch ------------------------------------------------------
extern "C" void kernel_launch(void* const* d_in, const int* in_sizes, int n_in,
                              void* d_out, int out_size) {
    const float* feats = (const float*)d_in[0];
    const int*   nbr   = (const int*)d_in[1];
    const float* W1    = (const float*)d_in[2];
    const float* g1    = (const float*)d_in[3];
    const float* b1    = (const float*)d_in[4];
    const float* W2    = (const float*)d_in[5];
    const float* g2    = (const float*)d_in[6];
    const float* b2    = (const float*)d_in[7];
    const float* Wsk   = (const float*)d_in[8];
    const float* gsk   = (const float*)d_in[9];
    const float* bsk   = (const float*)d_in[10];
    float* out = (float*)d_out;

    float *hpre, *respre, *skippre;
    __nv_bfloat16 *fhi, *flo, *hhi, *hlo, *w1hi, *w1lo, *w2hi, *w2lo, *wskhi, *wsklo;
    cudaGetSymbolAddress((void**)&hpre, g_hpre);
    cudaGetSymbolAddress((void**)&respre, g_respre);
    cudaGetSymbolAddress((void**)&skippre, g_skippre);
    cudaGetSymbolAddress((void**)&fhi, g_fhi);
    cudaGetSymbolAddress((void**)&flo, g_flo);
    cudaGetSymbolAddress((void**)&hhi, g_hhi);
    cudaGetSymbolAddress((void**)&hlo, g_hlo);
    cudaGetSymbolAddress((void**)&w1hi, g_w1hi);
    cudaGetSymbolAddress((void**)&w1lo, g_w1lo);
    cudaGetSymbolAddress((void**)&w2hi, g_w2hi);
    cudaGetSymbolAddress((void**)&w2lo, g_w2lo);
    cudaGetSymbolAddress((void**)&wskhi, g_wskhi);
    cudaGetSymbolAddress((void**)&wsklo, g_wsklo);

    const int SMEM_BYTES = NSTAGE * STAGE_B;  // 98304
    cudaFuncSetAttribute(mma_conv_kernel<true>,
                         cudaFuncAttributeMaxDynamicSharedMemorySize, SMEM_BYTES);
    cudaFuncSetAttribute(mma_conv_kernel<false>,
                         cudaFuncAttributeMaxDynamicSharedMemorySize, SMEM_BYTES);

    const int grid = NPART;  // 1563
    const long long total4 = (long long)NROWS * COUT / 4;
    const int egrid = (int)((total4 + 255) / 256);
    const long long f4 = (long long)NROWS * CIN1 / 4;

    // ---- prep (ordered so launch index 3 == conv1, which ncu captures)
    wsplit_kernel<<<(NTAPS * 128 * CIN1 + 255) / 256, 256>>>(W1, w1hi, w1lo, NTAPS, CIN1);
    xsplit_kernel<<<(int)((f4 + 255) / 256), 256>>>((const float4*)feats,
                                                    (uint2*)fhi, (uint2*)flo, f4);
    wsplit_kernel<<<(NTAPS * 128 * COUT + 255) / 256, 256>>>(W2, w2hi, w2lo, NTAPS, COUT);

    // ---- conv1: 27 taps, K=64  (launch index 3 -> profiled); stats -> pslot 0
    mma_conv_kernel<true><<<grid, 256, SMEM_BYTES>>>(fhi, flo, nbr,
                                                     w1hi, w1lo, hpre, NTAPS, CIN1, 1, 0);

    // ---- skip branch; stats -> pslot 1
    wsplit_kernel<<<(128 * CIN1 + 255) / 256, 256>>>(Wsk, wskhi, wsklo, 1, CIN1);
    mma_conv_kernel<false><<<grid, 256, SMEM_BYTES>>>(fhi, flo, nullptr,
                                                      wskhi, wsklo, skippre, 1, CIN1, 1, 1);

    // ---- BN1 finalize (from fused partials) + fused apply+split
    finalize_kernel<<<1, COUT>>>(g1, b1, 0, 0);
    bnsplit_kernel<<<egrid, 256>>>((const float4*)hpre, (uint2*)hhi, (uint2*)hlo);
    // ---- conv2: 27 taps, K=128; stats -> pslot 0
    mma_conv_kernel<true><<<grid, 256, SMEM_BYTES>>>(hhi, hlo, nbr,
                                                     w2hi, w2lo, respre, NTAPS, COUT, 2, 0);
    // ---- BN2 + BNskip finalize
    finalize_kernel<<<1, COUT>>>(g2, b2, 1, 0);
    finalize_kernel<<<1, COUT>>>(gsk, bsk, 2, 1);
    // ---- out = relu(bn(res) + bn(skip))
    final_kernel<<<egrid, 256>>>((float4*)out);
}

// round 11
// speedup vs baseline: 1.1768x; 1.1768x over previous
#include <cuda_runtime.h>
#include <cuda_bf16.h>
#include <cstdint>

#define NROWS 200000
#define CIN1  64
#define COUT  128
#define NTAPS 27
#define EPSBN 1e-5f
#define NPART 1563   // ceil(NROWS/128) == conv grid size

// ---------------- scratch (device globals; no allocation allowed) ----------
__device__ float g_hpre[(size_t)NROWS * COUT];    // conv1 pre-BN
__device__ float g_respre[(size_t)NROWS * COUT];  // conv2 pre-BN
__device__ float g_skippre[(size_t)NROWS * COUT]; // skip pre-BN
__device__ __nv_bfloat16 g_fhi[(size_t)NROWS * CIN1];
__device__ __nv_bfloat16 g_flo[(size_t)NROWS * CIN1];
__device__ __nv_bfloat16 g_hhi[(size_t)NROWS * COUT];
__device__ __nv_bfloat16 g_hlo[(size_t)NROWS * COUT];
__device__ __nv_bfloat16 g_w1hi[(size_t)NTAPS * COUT * CIN1];  // [tap][n][k]
__device__ __nv_bfloat16 g_w1lo[(size_t)NTAPS * COUT * CIN1];
__device__ __nv_bfloat16 g_w2hi[(size_t)NTAPS * COUT * COUT];
__device__ __nv_bfloat16 g_w2lo[(size_t)NTAPS * COUT * COUT];
__device__ __nv_bfloat16 g_wskhi[(size_t)COUT * CIN1];
__device__ __nv_bfloat16 g_wsklo[(size_t)COUT * CIN1];
__device__ float g_psum[2][NPART][COUT];   // fused per-CTA stats partials
__device__ float g_psq[2][NPART][COUT];
__device__ float g_inv[3][COUT];    // g * rsqrt(var+eps)
__device__ float g_shift[3][COUT];  // b - mean*inv

// ---------------- PTX helpers (baseline features only) -----------------------
__device__ __forceinline__ uint32_t smem_u32(const void* p) {
    uint32_t a;
    asm("{ .reg .u64 t; cvta.to.shared.u64 t, %1; cvt.u32.u64 %0, t; }"
        : "=r"(a) : "l"(p));
    return a;
}
__device__ __forceinline__ void cpasync16(uint32_t dst, const void* src, int srcsize) {
    asm volatile("cp.async.cg.shared.global [%0], [%1], 16, %2;"
                 :: "r"(dst), "l"(src), "r"(srcsize));
}
__device__ __forceinline__ void cpcommit() {
    asm volatile("cp.async.commit_group;");
}
__device__ __forceinline__ void ldm4(uint32_t* r, uint32_t addr) {
    asm volatile("ldmatrix.sync.aligned.m8n8.x4.shared.b16 {%0,%1,%2,%3}, [%4];"
                 : "=r"(r[0]), "=r"(r[1]), "=r"(r[2]), "=r"(r[3]) : "r"(addr));
}
__device__ __forceinline__ void mma16816(float* d, const uint32_t* a, const uint32_t* b) {
    asm volatile(
        "mma.sync.aligned.m16n8k16.row.col.f32.bf16.bf16.f32 "
        "{%0,%1,%2,%3},{%4,%5,%6,%7},{%8,%9},{%0,%1,%2,%3};"
        : "+f"(d[0]), "+f"(d[1]), "+f"(d[2]), "+f"(d[3])
        : "r"(a[0]), "r"(a[1]), "r"(a[2]), "r"(a[3]), "r"(b[0]), "r"(b[1]));
}

// smem tile geometry: 128 rows x 64B (32 bf16), XOR swizzle, no padding.
#define TILE_B 8192
#define NSTAGE 3
#define STAGE_B (4 * TILE_B)         // XH, XL, WH, WL = 32 KB
#define XH_OFF 0
#define XL_OFF TILE_B
#define WH_OFF (2 * TILE_B)
#define WL_OFF (3 * TILE_B)

__device__ __forceinline__ uint32_t sw_off(int row, int bytecol) {
    const int ch = bytecol >> 4;
    return (uint32_t)(row * 64) + (((uint32_t)(ch ^ ((row >> 1) & 3))) << 4);
}

// ---------------- HMMA gathered multi-tap GEMM -------------------------------
template <bool GATHER>
__global__ __launch_bounds__(256, 2)
void mma_conv_kernel(const __nv_bfloat16* __restrict__ Xhi,
                     const __nv_bfloat16* __restrict__ Xlo,
                     const int* __restrict__ nbr,
                     const __nv_bfloat16* __restrict__ Whi,
                     const __nv_bfloat16* __restrict__ Wlo,
                     float* __restrict__ Y, int ntaps, int xk, int cptsh,
                     int pslot) {
    extern __shared__ char smem[];
    const uint32_t sb = smem_u32(smem);
    const int tid = threadIdx.x;
    const int wid = tid >> 5;
    const int lid = tid & 31;
    const int row0 = blockIdx.x * 128;
    const int kmask = (1 << cptsh) - 1;
    const int nsub = ntaps << cptsh;

    const int wm = (wid & 1) * 64;      // warp M offset
    const int wn = (wid >> 1) * 32;     // warp N offset

    const int lr = tid >> 1;            // load row 0..127
    const int lc = (tid & 1) * 2;       // chunk pair 0/2

    float acc[4][4][4];
#pragma unroll
    for (int i = 0; i < 4; i++)
#pragma unroll
        for (int j = 0; j < 4; j++)
#pragma unroll
            for (int q = 0; q < 4; q++) acc[i][j][q] = 0.f;

    auto src_of = [&](int s) -> int {
        const int grow = row0 + lr;
        if (!GATHER) return grow;
        const int tap = s >> cptsh;
        return (grow < NROWS) ? __ldg(nbr + (size_t)tap * NROWS + grow) : NROWS;
    };

    auto load_stage = [&](int s, int src) {
        const int buf = s % NSTAGE;
        const int kc = s & kmask;
        const uint32_t st = sb + buf * STAGE_B;
        const bool val = (unsigned)src < (unsigned)NROWS;
        const int srow = val ? src : 0;
        const int sz = val ? 16 : 0;
        const __nv_bfloat16* xh = Xhi + (size_t)srow * xk + kc * 32;
        const __nv_bfloat16* xl = Xlo + (size_t)srow * xk + kc * 32;
        const int tap = s >> cptsh;
        const __nv_bfloat16* wh = Whi + ((size_t)tap * 128 + lr) * xk + kc * 32;
        const __nv_bfloat16* wl = Wlo + ((size_t)tap * 128 + lr) * xk + kc * 32;
        const int sel = (lr >> 1) & 3;
        const uint32_t rbase = st + lr * 64;
#pragma unroll
        for (int c = 0; c < 2; c++) {
            const uint32_t d = rbase + (((uint32_t)((lc + c) ^ sel)) << 4);
            cpasync16(d + XH_OFF, xh + (lc + c) * 8, sz);
            cpasync16(d + XL_OFF, xl + (lc + c) * 8, sz);
            cpasync16(d + WH_OFF, wh + (lc + c) * 8, 16);
            cpasync16(d + WL_OFF, wl + (lc + c) * 8, 16);
        }
    };

    // ---- prologue: 2 stages in flight
    {
        int s0 = src_of(0);
        load_stage(0, s0);
        cpcommit();
    }
    if (nsub > 1) {
        int s1 = src_of(1);
        load_stage(1, s1);
        cpcommit();
    }
    int src2 = (nsub > 2) ? src_of(2) : 0;

    // ---- precomputed fragment smem offsets (swizzle hoisted out of mainloop)
    const int b_nrow = (lid & 7) + ((lid >> 4) << 3);
    const int b_kof = ((lid >> 3) & 1) * 16;
    const int a_row = lid & 15;
    const int a_kof = (lid >> 4) * 16;
    uint32_t boff[2][2], aoff[2][4];
#pragma unroll
    for (int kh = 0; kh < 2; kh++) {
#pragma unroll
        for (int half = 0; half < 2; half++)
            boff[kh][half] = WH_OFF + sw_off(wn + half * 16 + b_nrow, kh * 32 + b_kof);
#pragma unroll
        for (int mi = 0; mi < 4; mi++)
            aoff[kh][mi] = XH_OFF + sw_off(wm + mi * 16 + a_row, kh * 32 + a_kof);
    }

    for (int s = 0; s < nsub; s++) {
        if (s + 2 < nsub) {
            load_stage(s + 2, src2);
            cpcommit();
            src2 = src_of(s + 3);   // prefetch gather index 3 stages ahead
            asm volatile("cp.async.wait_group 2;");
        } else if (s + 1 < nsub) {
            asm volatile("cp.async.wait_group 1;");
        } else {
            asm volatile("cp.async.wait_group 0;");
        }
        __syncthreads();

        const uint32_t st = sb + (s % NSTAGE) * STAGE_B;
#pragma unroll
        for (int kh = 0; kh < 2; kh++) {
            uint32_t bh[4][2], bl[4][2];
#pragma unroll
            for (int half = 0; half < 2; half++) {
                const uint32_t wa = st + boff[kh][half];
                uint32_t rg[4];
                ldm4(rg, wa);
                bh[half * 2][0] = rg[0]; bh[half * 2][1] = rg[1];
                bh[half * 2 + 1][0] = rg[2]; bh[half * 2 + 1][1] = rg[3];
                ldm4(rg, wa + (WL_OFF - WH_OFF));
                bl[half * 2][0] = rg[0]; bl[half * 2][1] = rg[1];
                bl[half * 2 + 1][0] = rg[2]; bl[half * 2 + 1][1] = rg[3];
            }
#pragma unroll
            for (int mi = 0; mi < 4; mi++) {
                const uint32_t aa = st + aoff[kh][mi];
                uint32_t ah[4], al[4];
                ldm4(ah, aa);
                ldm4(al, aa + (XL_OFF - XH_OFF));
#pragma unroll
                for (int ni = 0; ni < 4; ni++) {
                    mma16816(acc[mi][ni], ah, bh[ni]);
                    mma16816(acc[mi][ni], ah, bl[ni]);
                    mma16816(acc[mi][ni], al, bh[ni]);
                }
            }
        }
        __syncthreads();
    }

    // ---- epilogue 1: write fp32 tile
#pragma unroll
    for (int mi = 0; mi < 4; mi++) {
        const int m0 = row0 + wm + mi * 16 + (lid >> 2);
#pragma unroll
        for (int ni = 0; ni < 4; ni++) {
            const int col = wn + ni * 8 + 2 * (lid & 3);
            if (m0 < NROWS)
                *(float2*)(Y + (size_t)m0 * 128 + col) =
                    make_float2(acc[mi][ni][0], acc[mi][ni][1]);
            if (m0 + 8 < NROWS)
                *(float2*)(Y + (size_t)(m0 + 8) * 128 + col) =
                    make_float2(acc[mi][ni][2], acc[mi][ni][3]);
        }
    }

    // ---- epilogue 2: fused column stats (rows beyond NROWS contribute 0)
    float ts[8], tq[8];
#pragma unroll
    for (int ni = 0; ni < 4; ni++)
#pragma unroll
        for (int j = 0; j < 2; j++) {
            float s = 0.f, q = 0.f;
#pragma unroll
            for (int mi = 0; mi < 4; mi++) {
                float v0 = acc[mi][ni][j];
                float v1 = acc[mi][ni][j + 2];
                s += v0 + v1;
                q += v0 * v0 + v1 * v1;
            }
            ts[ni * 2 + j] = s;
            tq[ni * 2 + j] = q;
        }
#pragma unroll
    for (int o = 16; o >= 4; o >>= 1)
#pragma unroll
        for (int i = 0; i < 8; i++) {
            ts[i] += __shfl_down_sync(0xffffffffu, ts[i], o);
            tq[i] += __shfl_down_sync(0xffffffffu, tq[i], o);
        }
    __syncthreads();   // stage smem free for reuse
    float* ss = (float*)smem;          // [8][32]
    float* sq = ss + 256;
    if (lid < 4) {
#pragma unroll
        for (int ni = 0; ni < 4; ni++)
#pragma unroll
            for (int j = 0; j < 2; j++) {
                const int cl = ni * 8 + 2 * lid + j;
                ss[wid * 32 + cl] = ts[ni * 2 + j];
                sq[wid * 32 + cl] = tq[ni * 2 + j];
            }
    }
    __syncthreads();
    if (tid < COUT) {
        const int w0 = (tid >> 5) * 2;
        const int c = tid & 31;
        g_psum[pslot][blockIdx.x][tid] = ss[w0 * 32 + c] + ss[w0 * 32 + 32 + c];
        g_psq[pslot][blockIdx.x][tid]  = sq[w0 * 32 + c] + sq[w0 * 32 + 32 + c];
    }
}

// ---------------- prep: W transpose + bf16 split -----------------------------
__global__ void wsplit_kernel(const float* __restrict__ W,
                              __nv_bfloat16* __restrict__ hi,
                              __nv_bfloat16* __restrict__ lo, int taps, int K) {
    int i = blockIdx.x * blockDim.x + threadIdx.x;
    int total = taps * 128 * K;
    if (i >= total) return;
    int kk = i % K;
    int t2 = i / K;
    int n = t2 & 127;
    int tap = t2 >> 7;
    float v = __ldg(W + ((size_t)tap * K + kk) * 128 + n);
    __nv_bfloat16 h = __float2bfloat16(v);
    hi[i] = h;
    lo[i] = __float2bfloat16(v - __bfloat162float(h));
}

// ---------------- prep: feats bf16 split (vector) ----------------------------
__global__ void xsplit_kernel(const float4* __restrict__ X,
                              uint2* __restrict__ hi, uint2* __restrict__ lo,
                              long long n4) {
    long long i = (long long)blockIdx.x * blockDim.x + threadIdx.x;
    if (i >= n4) return;
    float4 v = X[i];
    __nv_bfloat16 hx = __float2bfloat16(v.x), hy = __float2bfloat16(v.y);
    __nv_bfloat16 hz = __float2bfloat16(v.z), hw = __float2bfloat16(v.w);
    __nv_bfloat162 h01, h23, l01, l23;
    h01.x = hx; h01.y = hy; h23.x = hz; h23.y = hw;
    l01.x = __float2bfloat16(v.x - __bfloat162float(hx));
    l01.y = __float2bfloat16(v.y - __bfloat162float(hy));
    l23.x = __float2bfloat16(v.z - __bfloat162float(hz));
    l23.y = __float2bfloat16(v.w - __bfloat162float(hw));
    hi[i] = make_uint2(*(uint32_t*)&h01, *(uint32_t*)&h23);
    lo[i] = make_uint2(*(uint32_t*)&l01, *(uint32_t*)&l23);
}

// ---------------- BN finalize from fused partials (parallel) ------------------
// 1024 threads: 8 chunks x 128 cols; chunk c sums partial rows [c*196, ...).
__global__ void finalize_kernel(const float* __restrict__ g,
                                const float* __restrict__ b, int slot, int pslot) {
    __shared__ float ss[8][COUT];
    __shared__ float sq[8][COUT];
    const int col = threadIdx.x & (COUT - 1);
    const int chunk = threadIdx.x >> 7;     // 0..7
    const int beg = chunk * 196;
    const int end = (chunk == 7) ? NPART : (beg + 196);
    float s0 = 0.f, s1 = 0.f, q0 = 0.f, q1 = 0.f;
    int i = beg;
    for (; i + 1 < end; i += 2) {
        s0 += g_psum[pslot][i][col];
        q0 += g_psq[pslot][i][col];
        s1 += g_psum[pslot][i + 1][col];
        q1 += g_psq[pslot][i + 1][col];
    }
    for (; i < end; i++) {
        s0 += g_psum[pslot][i][col];
        q0 += g_psq[pslot][i][col];
    }
    ss[chunk][col] = s0 + s1;
    sq[chunk][col] = q0 + q1;
    __syncthreads();
    if (chunk == 0) {
        float s = 0.f, q = 0.f;
#pragma unroll
        for (int c = 0; c < 8; c++) { s += ss[c][col]; q += sq[c][col]; }
        float mean = s * (1.0f / NROWS);
        float var = q * (1.0f / NROWS) - mean * mean;
        float inv = g[col] * rsqrtf(var + EPSBN);
        g_inv[slot][col] = inv;
        g_shift[slot][col] = b[col] - mean * inv;
    }
}

// ---------------- BN apply (slot 0) fused with bf16 split --------------------
__global__ void bnsplit_kernel(const float4* __restrict__ X,
                               uint2* __restrict__ hi, uint2* __restrict__ lo) {
    long long i = (long long)blockIdx.x * blockDim.x + threadIdx.x;
    const long long total = (long long)NROWS * COUT / 4;
    if (i >= total) return;
    int c4 = (int)(i & (COUT / 4 - 1)) * 4;
    float4 v = X[i];
    v.x = v.x * g_inv[0][c4 + 0] + g_shift[0][c4 + 0];
    v.y = v.y * g_inv[0][c4 + 1] + g_shift[0][c4 + 1];
    v.z = v.z * g_inv[0][c4 + 2] + g_shift[0][c4 + 2];
    v.w = v.w * g_inv[0][c4 + 3] + g_shift[0][c4 + 3];
    __nv_bfloat16 hx = __float2bfloat16(v.x), hy = __float2bfloat16(v.y);
    __nv_bfloat16 hz = __float2bfloat16(v.z), hw = __float2bfloat16(v.w);
    __nv_bfloat162 h01, h23, l01, l23;
    h01.x = hx; h01.y = hy; h23.x = hz; h23.y = hw;
    l01.x = __float2bfloat16(v.x - __bfloat162float(hx));
    l01.y = __float2bfloat16(v.y - __bfloat162float(hy));
    l23.x = __float2bfloat16(v.z - __bfloat162float(hz));
    l23.y = __float2bfloat16(v.w - __bfloat162float(hw));
    hi[i] = make_uint2(*(uint32_t*)&h01, *(uint32_t*)&h23);
    lo[i] = make_uint2(*(uint32_t*)&l01, *(uint32_t*)&l23);
}

// ---------------- final: relu(bn(res) + bn(skip)) ----------------------------
__global__ void final_kernel(float4* __restrict__ out) {
    long long i = (long long)blockIdx.x * blockDim.x + threadIdx.x;
    const long long total = (long long)NROWS * COUT / 4;
    if (i >= total) return;
    int c4 = (int)(i & (COUT / 4 - 1)) * 4;
    const float4 r = ((const float4*)g_respre)[i];
    const float4 s = ((const float4*)g_skippre)[i];
    float4 o;
    o.x = fmaxf(r.x * g_inv[1][c4 + 0] + g_shift[1][c4 + 0] +
                s.x * g_inv[2][c4 + 0] + g_shift[2][c4 + 0], 0.f);
    o.y = fmaxf(r.y * g_inv[1][c4 + 1] + g_shift[1][c4 + 1] +
                s.y * g_inv[2][c4 + 1] + g_shift[2][c4 + 1], 0.f);
    o.z = fmaxf(r.z * g_inv[1][c4 + 2] + g_shift[1][c4 + 2] +
                s.z * g_inv[2][c4 + 2] + g_shift[2][c4 + 2], 0.f);
    o.w = fmaxf(r.w * g_inv[1][c4 + 3] + g_shift[1][c4 + 3] +
                s.w * g_inv[2][c4 + 3] + g_shift[2][c4 + 3], 0.f);
    out[i] = o;
}

// ---------------- launch ------------------------------------------------------
extern "C" void kernel_launch(void* const* d_in, const int* in_sizes, int n_in,
                              void* d_out, int out_size) {
    const float* feats = (const float*)d_in[0];
    const int*   nbr   = (const int*)d_in[1];
    const float* W1    = (const float*)d_in[2];
    const float* g1    = (const float*)d_in[3];
    const float* b1    = (const float*)d_in[4];
    const float* W2    = (const float*)d_in[5];
    const float* g2    = (const float*)d_in[6];
    const float* b2    = (const float*)d_in[7];
    const float* Wsk   = (const float*)d_in[8];
    const float* gsk   = (const float*)d_in[9];
    const float* bsk   = (const float*)d_in[10];
    float* out = (float*)d_out;

    float *hpre, *respre, *skippre;
    __nv_bfloat16 *fhi, *flo, *hhi, *hlo, *w1hi, *w1lo, *w2hi, *w2lo, *wskhi, *wsklo;
    cudaGetSymbolAddress((void**)&hpre, g_hpre);
    cudaGetSymbolAddress((void**)&respre, g_respre);
    cudaGetSymbolAddress((void**)&skippre, g_skippre);
    cudaGetSymbolAddress((void**)&fhi, g_fhi);
    cudaGetSymbolAddress((void**)&flo, g_flo);
    cudaGetSymbolAddress((void**)&hhi, g_hhi);
    cudaGetSymbolAddress((void**)&hlo, g_hlo);
    cudaGetSymbolAddress((void**)&w1hi, g_w1hi);
    cudaGetSymbolAddress((void**)&w1lo, g_w1lo);
    cudaGetSymbolAddress((void**)&w2hi, g_w2hi);
    cudaGetSymbolAddress((void**)&w2lo, g_w2lo);
    cudaGetSymbolAddress((void**)&wskhi, g_wskhi);
    cudaGetSymbolAddress((void**)&wsklo, g_wsklo);

    const int SMEM_BYTES = NSTAGE * STAGE_B;  // 98304
    cudaFuncSetAttribute(mma_conv_kernel<true>,
                         cudaFuncAttributeMaxDynamicSharedMemorySize, SMEM_BYTES);
    cudaFuncSetAttribute(mma_conv_kernel<false>,
                         cudaFuncAttributeMaxDynamicSharedMemorySize, SMEM_BYTES);

    const int grid = NPART;  // 1563
    const long long total4 = (long long)NROWS * COUT / 4;
    const int egrid = (int)((total4 + 255) / 256);
    const long long f4 = (long long)NROWS * CIN1 / 4;

    // ---- prep (ordered so launch index 3 == conv1, which ncu captures)
    wsplit_kernel<<<(NTAPS * 128 * CIN1 + 255) / 256, 256>>>(W1, w1hi, w1lo, NTAPS, CIN1);
    xsplit_kernel<<<(int)((f4 + 255) / 256), 256>>>((const float4*)feats,
                                                    (uint2*)fhi, (uint2*)flo, f4);
    wsplit_kernel<<<(NTAPS * 128 * COUT + 255) / 256, 256>>>(W2, w2hi, w2lo, NTAPS, COUT);

    // ---- conv1: 27 taps, K=64  (launch index 3 -> profiled); stats -> pslot 0
    mma_conv_kernel<true><<<grid, 256, SMEM_BYTES>>>(fhi, flo, nbr,
                                                     w1hi, w1lo, hpre, NTAPS, CIN1, 1, 0);

    // ---- skip branch; stats -> pslot 1
    wsplit_kernel<<<(128 * CIN1 + 255) / 256, 256>>>(Wsk, wskhi, wsklo, 1, CIN1);
    mma_conv_kernel<false><<<grid, 256, SMEM_BYTES>>>(fhi, flo, nullptr,
                                                      wskhi, wsklo, skippre, 1, CIN1, 1, 1);

    // ---- BN1 finalize (parallel) + fused apply+split
    finalize_kernel<<<1, 1024>>>(g1, b1, 0, 0);
    bnsplit_kernel<<<egrid, 256>>>((const float4*)hpre, (uint2*)hhi, (uint2*)hlo);
    // ---- conv2: 27 taps, K=128; stats -> pslot 0
    mma_conv_kernel<true><<<grid, 256, SMEM_BYTES>>>(hhi, hlo, nbr,
                                                     w2hi, w2lo, respre, NTAPS, COUT, 2, 0);
    // ---- BN2 + BNskip finalize
    finalize_kernel<<<1, 1024>>>(g2, b2, 1, 0);
    finalize_kernel<<<1, 1024>>>(gsk, bsk, 2, 1);
    // ---- out = relu(bn(res) + bn(skip))
    final_kernel<<<egrid, 256>>>((float4*)out);
}

// round 12
// speedup vs baseline: 1.5965x; 1.3567x over previous
#include <cuda_runtime.h>
#include <cuda_fp16.h>
#include <cstdint>

#define NROWS 200000
#define CIN1  64
#define COUT  128
#define NTAPS 27
#define EPSBN 1e-5f
#define NPART 1563   // ceil(NROWS/128) == conv grid size

// ---------------- scratch (device globals; no allocation allowed) ----------
__device__ float g_hpre[(size_t)NROWS * COUT];    // conv1 pre-BN
__device__ float g_respre[(size_t)NROWS * COUT];  // conv2 pre-BN
__device__ float g_skippre[(size_t)NROWS * COUT]; // skip pre-BN
__device__ __half g_fhi[(size_t)NROWS * CIN1];
__device__ __half g_flo[(size_t)NROWS * CIN1];
__device__ __half g_hhi[(size_t)NROWS * COUT];
__device__ __half g_hlo[(size_t)NROWS * COUT];
__device__ __half g_w1hi[(size_t)NTAPS * COUT * CIN1];  // [tap][n][k]
__device__ __half g_w2hi[(size_t)NTAPS * COUT * COUT];
__device__ __half g_wskhi[(size_t)COUT * CIN1];
__device__ float g_psum[2][NPART][COUT];   // fused per-CTA stats partials
__device__ float g_psq[2][NPART][COUT];
__device__ float g_inv[3][COUT];    // g * rsqrt(var+eps)
__device__ float g_shift[3][COUT];  // b - mean*inv

// ---------------- PTX helpers (baseline features only) -----------------------
__device__ __forceinline__ uint32_t smem_u32(const void* p) {
    uint32_t a;
    asm("{ .reg .u64 t; cvta.to.shared.u64 t, %1; cvt.u32.u64 %0, t; }"
        : "=r"(a) : "l"(p));
    return a;
}
__device__ __forceinline__ void cpasync16(uint32_t dst, const void* src, int srcsize) {
    asm volatile("cp.async.cg.shared.global [%0], [%1], 16, %2;"
                 :: "r"(dst), "l"(src), "r"(srcsize));
}
__device__ __forceinline__ void cpcommit() {
    asm volatile("cp.async.commit_group;");
}
__device__ __forceinline__ void ldm4(uint32_t* r, uint32_t addr) {
    asm volatile("ldmatrix.sync.aligned.m8n8.x4.shared.b16 {%0,%1,%2,%3}, [%4];"
                 : "=r"(r[0]), "=r"(r[1]), "=r"(r[2]), "=r"(r[3]) : "r"(addr));
}
__device__ __forceinline__ void mma16816(float* d, const uint32_t* a, const uint32_t* b) {
    asm volatile(
        "mma.sync.aligned.m16n8k16.row.col.f32.f16.f16.f32 "
        "{%0,%1,%2,%3},{%4,%5,%6,%7},{%8,%9},{%0,%1,%2,%3};"
        : "+f"(d[0]), "+f"(d[1]), "+f"(d[2]), "+f"(d[3])
        : "r"(a[0]), "r"(a[1]), "r"(a[2]), "r"(a[3]), "r"(b[0]), "r"(b[1]));
}

// smem tile geometry: 128 rows x 64B (32 fp16), XOR swizzle, no padding.
#define TILE_B 8192
#define NSTAGE 3
#define STAGE_B (3 * TILE_B)         // XH, XL, WH = 24 KB
#define XH_OFF 0
#define XL_OFF TILE_B
#define WH_OFF (2 * TILE_B)

__device__ __forceinline__ uint32_t sw_off(int row, int bytecol) {
    const int ch = bytecol >> 4;
    return (uint32_t)(row * 64) + (((uint32_t)(ch ^ ((row >> 1) & 3))) << 4);
}

// ---------------- HMMA gathered multi-tap GEMM (fp16 2-term split) -----------
// Y = sum_s gather(Ahi+Alo)[128,32] @ Bhi[32,128]; dropped term = B fp16 rounding.
template <bool GATHER>
__global__ __launch_bounds__(256, 2)
void mma_conv_kernel(const __half* __restrict__ Xhi,
                     const __half* __restrict__ Xlo,
                     const int* __restrict__ nbr,
                     const __half* __restrict__ Whi,
                     float* __restrict__ Y, int ntaps, int xk, int cptsh,
                     int pslot) {
    extern __shared__ char smem[];
    const uint32_t sb = smem_u32(smem);
    const int tid = threadIdx.x;
    const int wid = tid >> 5;
    const int lid = tid & 31;
    const int row0 = blockIdx.x * 128;
    const int kmask = (1 << cptsh) - 1;
    const int nsub = ntaps << cptsh;

    const int wm = (wid & 1) * 64;      // warp M offset
    const int wn = (wid >> 1) * 32;     // warp N offset

    const int lr = tid >> 1;            // load row 0..127
    const int lc = (tid & 1) * 2;       // chunk pair 0/2

    float acc[4][4][4];
#pragma unroll
    for (int i = 0; i < 4; i++)
#pragma unroll
        for (int j = 0; j < 4; j++)
#pragma unroll
            for (int q = 0; q < 4; q++) acc[i][j][q] = 0.f;

    auto src_of = [&](int s) -> int {
        const int grow = row0 + lr;
        if (!GATHER) return grow;
        const int tap = s >> cptsh;
        return (grow < NROWS) ? __ldg(nbr + (size_t)tap * NROWS + grow) : NROWS;
    };

    auto load_stage = [&](int s, int src) {
        const int buf = s % NSTAGE;
        const int kc = s & kmask;
        const uint32_t st = sb + buf * STAGE_B;
        const bool val = (unsigned)src < (unsigned)NROWS;
        const int srow = val ? src : 0;
        const int sz = val ? 16 : 0;
        const __half* xh = Xhi + (size_t)srow * xk + kc * 32;
        const __half* xl = Xlo + (size_t)srow * xk + kc * 32;
        const int tap = s >> cptsh;
        const __half* wh = Whi + ((size_t)tap * 128 + lr) * xk + kc * 32;
        const int sel = (lr >> 1) & 3;
        const uint32_t rbase = st + lr * 64;
#pragma unroll
        for (int c = 0; c < 2; c++) {
            const uint32_t d = rbase + (((uint32_t)((lc + c) ^ sel)) << 4);
            cpasync16(d + XH_OFF, xh + (lc + c) * 8, sz);
            cpasync16(d + XL_OFF, xl + (lc + c) * 8, sz);
            cpasync16(d + WH_OFF, wh + (lc + c) * 8, 16);
        }
    };

    // ---- prologue: 2 stages in flight
    {
        int s0 = src_of(0);
        load_stage(0, s0);
        cpcommit();
    }
    if (nsub > 1) {
        int s1 = src_of(1);
        load_stage(1, s1);
        cpcommit();
    }
    int src2 = (nsub > 2) ? src_of(2) : 0;

    // ---- precomputed fragment smem offsets (swizzle hoisted out of mainloop)
    const int b_nrow = (lid & 7) + ((lid >> 4) << 3);
    const int b_kof = ((lid >> 3) & 1) * 16;
    const int a_row = lid & 15;
    const int a_kof = (lid >> 4) * 16;
    uint32_t boff[2][2], aoff[2][4];
#pragma unroll
    for (int kh = 0; kh < 2; kh++) {
#pragma unroll
        for (int half = 0; half < 2; half++)
            boff[kh][half] = WH_OFF + sw_off(wn + half * 16 + b_nrow, kh * 32 + b_kof);
#pragma unroll
        for (int mi = 0; mi < 4; mi++)
            aoff[kh][mi] = XH_OFF + sw_off(wm + mi * 16 + a_row, kh * 32 + a_kof);
    }

    for (int s = 0; s < nsub; s++) {
        if (s + 2 < nsub) {
            load_stage(s + 2, src2);
            cpcommit();
            src2 = src_of(s + 3);   // prefetch gather index 3 stages ahead
            asm volatile("cp.async.wait_group 2;");
        } else if (s + 1 < nsub) {
            asm volatile("cp.async.wait_group 1;");
        } else {
            asm volatile("cp.async.wait_group 0;");
        }
        __syncthreads();

        const uint32_t st = sb + (s % NSTAGE) * STAGE_B;
#pragma unroll
        for (int kh = 0; kh < 2; kh++) {
            uint32_t bh[4][2];
#pragma unroll
            for (int half = 0; half < 2; half++) {
                const uint32_t wa = st + boff[kh][half];
                uint32_t rg[4];
                ldm4(rg, wa);
                bh[half * 2][0] = rg[0]; bh[half * 2][1] = rg[1];
                bh[half * 2 + 1][0] = rg[2]; bh[half * 2 + 1][1] = rg[3];
            }
#pragma unroll
            for (int mi = 0; mi < 4; mi++) {
                const uint32_t aa = st + aoff[kh][mi];
                uint32_t ah[4], al[4];
                ldm4(ah, aa);
                ldm4(al, aa + (XL_OFF - XH_OFF));
#pragma unroll
                for (int ni = 0; ni < 4; ni++) {
                    mma16816(acc[mi][ni], ah, bh[ni]);
                    mma16816(acc[mi][ni], al, bh[ni]);
                }
            }
        }
        __syncthreads();
    }

    // ---- epilogue 1: write fp32 tile
#pragma unroll
    for (int mi = 0; mi < 4; mi++) {
        const int m0 = row0 + wm + mi * 16 + (lid >> 2);
#pragma unroll
        for (int ni = 0; ni < 4; ni++) {
            const int col = wn + ni * 8 + 2 * (lid & 3);
            if (m0 < NROWS)
                *(float2*)(Y + (size_t)m0 * 128 + col) =
                    make_float2(acc[mi][ni][0], acc[mi][ni][1]);
            if (m0 + 8 < NROWS)
                *(float2*)(Y + (size_t)(m0 + 8) * 128 + col) =
                    make_float2(acc[mi][ni][2], acc[mi][ni][3]);
        }
    }

    // ---- epilogue 2: fused column stats (rows beyond NROWS contribute 0)
    float ts[8], tq[8];
#pragma unroll
    for (int ni = 0; ni < 4; ni++)
#pragma unroll
        for (int j = 0; j < 2; j++) {
            float s = 0.f, q = 0.f;
#pragma unroll
            for (int mi = 0; mi < 4; mi++) {
                float v0 = acc[mi][ni][j];
                float v1 = acc[mi][ni][j + 2];
                s += v0 + v1;
                q += v0 * v0 + v1 * v1;
            }
            ts[ni * 2 + j] = s;
            tq[ni * 2 + j] = q;
        }
#pragma unroll
    for (int o = 16; o >= 4; o >>= 1)
#pragma unroll
        for (int i = 0; i < 8; i++) {
            ts[i] += __shfl_down_sync(0xffffffffu, ts[i], o);
            tq[i] += __shfl_down_sync(0xffffffffu, tq[i], o);
        }
    __syncthreads();   // stage smem free for reuse
    float* ss = (float*)smem;          // [8][32]
    float* sq = ss + 256;
    if (lid < 4) {
#pragma unroll
        for (int ni = 0; ni < 4; ni++)
#pragma unroll
            for (int j = 0; j < 2; j++) {
                const int cl = ni * 8 + 2 * lid + j;
                ss[wid * 32 + cl] = ts[ni * 2 + j];
                sq[wid * 32 + cl] = tq[ni * 2 + j];
            }
    }
    __syncthreads();
    if (tid < COUT) {
        const int w0 = (tid >> 5) * 2;
        const int c = tid & 31;
        g_psum[pslot][blockIdx.x][tid] = ss[w0 * 32 + c] + ss[w0 * 32 + 32 + c];
        g_psq[pslot][blockIdx.x][tid]  = sq[w0 * 32 + c] + sq[w0 * 32 + 32 + c];
    }
}

// ---------------- prep: W transpose + fp16 convert ----------------------------
__global__ void wsplit_kernel(const float* __restrict__ W,
                              __half* __restrict__ hi, int taps, int K) {
    int i = blockIdx.x * blockDim.x + threadIdx.x;
    int total = taps * 128 * K;
    if (i >= total) return;
    int kk = i % K;
    int t2 = i / K;
    int n = t2 & 127;
    int tap = t2 >> 7;
    float v = __ldg(W + ((size_t)tap * K + kk) * 128 + n);
    hi[i] = __float2half_rn(v);
}

// ---------------- prep: feats fp16 split (vector) -----------------------------
__global__ void xsplit_kernel(const float4* __restrict__ X,
                              uint2* __restrict__ hi, uint2* __restrict__ lo,
                              long long n4) {
    long long i = (long long)blockIdx.x * blockDim.x + threadIdx.x;
    if (i >= n4) return;
    float4 v = X[i];
    __half hx = __float2half_rn(v.x), hy = __float2half_rn(v.y);
    __half hz = __float2half_rn(v.z), hw = __float2half_rn(v.w);
    __half2 h01 = __halves2half2(hx, hy), h23 = __halves2half2(hz, hw);
    __half2 l01 = __halves2half2(__float2half_rn(v.x - __half2float(hx)),
                                 __float2half_rn(v.y - __half2float(hy)));
    __half2 l23 = __halves2half2(__float2half_rn(v.z - __half2float(hz)),
                                 __float2half_rn(v.w - __half2float(hw)));
    hi[i] = make_uint2(*(uint32_t*)&h01, *(uint32_t*)&h23);
    lo[i] = make_uint2(*(uint32_t*)&l01, *(uint32_t*)&l23);
}

// ---------------- BN finalize from fused partials (parallel) ------------------
__global__ void finalize_kernel(const float* __restrict__ g,
                                const float* __restrict__ b, int slot, int pslot) {
    __shared__ float ss[8][COUT];
    __shared__ float sq[8][COUT];
    const int col = threadIdx.x & (COUT - 1);
    const int chunk = threadIdx.x >> 7;     // 0..7
    const int beg = chunk * 196;
    const int end = (chunk == 7) ? NPART : (beg + 196);
    float s0 = 0.f, s1 = 0.f, q0 = 0.f, q1 = 0.f;
    int i = beg;
    for (; i + 1 < end; i += 2) {
        s0 += g_psum[pslot][i][col];
        q0 += g_psq[pslot][i][col];
        s1 += g_psum[pslot][i + 1][col];
        q1 += g_psq[pslot][i + 1][col];
    }
    for (; i < end; i++) {
        s0 += g_psum[pslot][i][col];
        q0 += g_psq[pslot][i][col];
    }
    ss[chunk][col] = s0 + s1;
    sq[chunk][col] = q0 + q1;
    __syncthreads();
    if (chunk == 0) {
        float s = 0.f, q = 0.f;
#pragma unroll
        for (int c = 0; c < 8; c++) { s += ss[c][col]; q += sq[c][col]; }
        float mean = s * (1.0f / NROWS);
        float var = q * (1.0f / NROWS) - mean * mean;
        float inv = g[col] * rsqrtf(var + EPSBN);
        g_inv[slot][col] = inv;
        g_shift[slot][col] = b[col] - mean * inv;
    }
}

// ---------------- BN apply (slot 0) fused with fp16 split ---------------------
__global__ void bnsplit_kernel(const float4* __restrict__ X,
                               uint2* __restrict__ hi, uint2* __restrict__ lo) {
    long long i = (long long)blockIdx.x * blockDim.x + threadIdx.x;
    const long long total = (long long)NROWS * COUT / 4;
    if (i >= total) return;
    int c4 = (int)(i & (COUT / 4 - 1)) * 4;
    float4 v = X[i];
    v.x = v.x * g_inv[0][c4 + 0] + g_shift[0][c4 + 0];
    v.y = v.y * g_inv[0][c4 + 1] + g_shift[0][c4 + 1];
    v.z = v.z * g_inv[0][c4 + 2] + g_shift[0][c4 + 2];
    v.w = v.w * g_inv[0][c4 + 3] + g_shift[0][c4 + 3];
    __half hx = __float2half_rn(v.x), hy = __float2half_rn(v.y);
    __half hz = __float2half_rn(v.z), hw = __float2half_rn(v.w);
    __half2 h01 = __halves2half2(hx, hy), h23 = __halves2half2(hz, hw);
    __half2 l01 = __halves2half2(__float2half_rn(v.x - __half2float(hx)),
                                 __float2half_rn(v.y - __half2float(hy)));
    __half2 l23 = __halves2half2(__float2half_rn(v.z - __half2float(hz)),
                                 __float2half_rn(v.w - __half2float(hw)));
    hi[i] = make_uint2(*(uint32_t*)&h01, *(uint32_t*)&h23);
    lo[i] = make_uint2(*(uint32_t*)&l01, *(uint32_t*)&l23);
}

// ---------------- final: relu(bn(res) + bn(skip)) ----------------------------
__global__ void final_kernel(float4* __restrict__ out) {
    long long i = (long long)blockIdx.x * blockDim.x + threadIdx.x;
    const long long total = (long long)NROWS * COUT / 4;
    if (i >= total) return;
    int c4 = (int)(i & (COUT / 4 - 1)) * 4;
    const float4 r = ((const float4*)g_respre)[i];
    const float4 s = ((const float4*)g_skippre)[i];
    float4 o;
    o.x = fmaxf(r.x * g_inv[1][c4 + 0] + g_shift[1][c4 + 0] +
                s.x * g_inv[2][c4 + 0] + g_shift[2][c4 + 0], 0.f);
    o.y = fmaxf(r.y * g_inv[1][c4 + 1] + g_shift[1][c4 + 1] +
                s.y * g_inv[2][c4 + 1] + g_shift[2][c4 + 1], 0.f);
    o.z = fmaxf(r.z * g_inv[1][c4 + 2] + g_shift[1][c4 + 2] +
                s.z * g_inv[2][c4 + 2] + g_shift[2][c4 + 2], 0.f);
    o.w = fmaxf(r.w * g_inv[1][c4 + 3] + g_shift[1][c4 + 3] +
                s.w * g_inv[2][c4 + 3] + g_shift[2][c4 + 3], 0.f);
    out[i] = o;
}

// ---------------- launch ------------------------------------------------------
extern "C" void kernel_launch(void* const* d_in, const int* in_sizes, int n_in,
                              void* d_out, int out_size) {
    const float* feats = (const float*)d_in[0];
    const int*   nbr   = (const int*)d_in[1];
    const float* W1    = (const float*)d_in[2];
    const float* g1    = (const float*)d_in[3];
    const float* b1    = (const float*)d_in[4];
    const float* W2    = (const float*)d_in[5];
    const float* g2    = (const float*)d_in[6];
    const float* b2    = (const float*)d_in[7];
    const float* Wsk   = (const float*)d_in[8];
    const float* gsk   = (const float*)d_in[9];
    const float* bsk   = (const float*)d_in[10];
    float* out = (float*)d_out;

    float *hpre, *respre, *skippre;
    __half *fhi, *flo, *hhi, *hlo, *w1hi, *w2hi, *wskhi;
    cudaGetSymbolAddress((void**)&hpre, g_hpre);
    cudaGetSymbolAddress((void**)&respre, g_respre);
    cudaGetSymbolAddress((void**)&skippre, g_skippre);
    cudaGetSymbolAddress((void**)&fhi, g_fhi);
    cudaGetSymbolAddress((void**)&flo, g_flo);
    cudaGetSymbolAddress((void**)&hhi, g_hhi);
    cudaGetSymbolAddress((void**)&hlo, g_hlo);
    cudaGetSymbolAddress((void**)&w1hi, g_w1hi);
    cudaGetSymbolAddress((void**)&w2hi, g_w2hi);
    cudaGetSymbolAddress((void**)&wskhi, g_wskhi);

    const int SMEM_BYTES = NSTAGE * STAGE_B;  // 73728
    cudaFuncSetAttribute(mma_conv_kernel<true>,
                         cudaFuncAttributeMaxDynamicSharedMemorySize, SMEM_BYTES);
    cudaFuncSetAttribute(mma_conv_kernel<false>,
                         cudaFuncAttributeMaxDynamicSharedMemorySize, SMEM_BYTES);

    const int grid = NPART;  // 1563
    const long long total4 = (long long)NROWS * COUT / 4;
    const int egrid = (int)((total4 + 255) / 256);
    const long long f4 = (long long)NROWS * CIN1 / 4;

    // ---- prep (ordered so launch index 3 == conv1, which ncu captures)
    wsplit_kernel<<<(NTAPS * 128 * CIN1 + 255) / 256, 256>>>(W1, w1hi, NTAPS, CIN1);
    xsplit_kernel<<<(int)((f4 + 255) / 256), 256>>>((const float4*)feats,
                                                    (uint2*)fhi, (uint2*)flo, f4);
    wsplit_kernel<<<(NTAPS * 128 * COUT + 255) / 256, 256>>>(W2, w2hi, NTAPS, COUT);

    // ---- conv1: 27 taps, K=64  (launch index 3 -> profiled); stats -> pslot 0
    mma_conv_kernel<true><<<grid, 256, SMEM_BYTES>>>(fhi, flo, nbr,
                                                     w1hi, hpre, NTAPS, CIN1, 1, 0);

    // ---- skip branch; stats -> pslot 1
    wsplit_kernel<<<(128 * CIN1 + 255) / 256, 256>>>(Wsk, wskhi, 1, CIN1);
    mma_conv_kernel<false><<<grid, 256, SMEM_BYTES>>>(fhi, flo, nullptr,
                                                      wskhi, skippre, 1, CIN1, 1, 1);

    // ---- BN1 finalize (parallel) + fused apply+split
    finalize_kernel<<<1, 1024>>>(g1, b1, 0, 0);
    bnsplit_kernel<<<egrid, 256>>>((const float4*)hpre, (uint2*)hhi, (uint2*)hlo);
    // ---- conv2: 27 taps, K=128; stats -> pslot 0
    mma_conv_kernel<true><<<grid, 256, SMEM_BYTES>>>(hhi, hlo, nbr,
                                                     w2hi, respre, NTAPS, COUT, 2, 0);
    // ---- BN2 + BNskip finalize
    finalize_kernel<<<1, 1024>>>(g2, b2, 1, 0);
    finalize_kernel<<<1, 1024>>>(gsk, bsk, 2, 1);
    // ---- out = relu(bn(res) + bn(skip))
    final_kernel<<<egrid, 256>>>((float4*)out);
}

// round 13
// speedup vs baseline: 2.5179x; 1.5771x over previous
#include <cuda_runtime.h>
#include <cuda_fp16.h>
#include <cstdint>

#define NROWS 200000
#define CIN1  64
#define COUT  128
#define NTAPS 27
#define EPSBN 1e-5f
#define NPART 1563   // ceil(NROWS/128) == conv grid size

// ---------------- scratch (device globals; no allocation allowed) ----------
__device__ float g_hpre[(size_t)NROWS * COUT];    // conv1 pre-BN
__device__ float g_respre[(size_t)NROWS * COUT];  // conv2 pre-BN
__device__ float g_skippre[(size_t)NROWS * COUT]; // skip pre-BN
__device__ __half g_fh[(size_t)NROWS * CIN1];
__device__ __half g_hh[(size_t)NROWS * COUT];
__device__ __half g_w1h[(size_t)NTAPS * COUT * CIN1];  // [tap][n][k]
__device__ __half g_w2h[(size_t)NTAPS * COUT * COUT];
__device__ __half g_wskh[(size_t)COUT * CIN1];
__device__ float g_psum[2][NPART][COUT];   // fused per-CTA stats partials
__device__ float g_psq[2][NPART][COUT];
__device__ float g_inv[3][COUT];    // g * rsqrt(var+eps)
__device__ float g_shift[3][COUT];  // b - mean*inv

// ---------------- PTX helpers (baseline features only) -----------------------
__device__ __forceinline__ uint32_t smem_u32(const void* p) {
    uint32_t a;
    asm("{ .reg .u64 t; cvta.to.shared.u64 t, %1; cvt.u32.u64 %0, t; }"
        : "=r"(a) : "l"(p));
    return a;
}
__device__ __forceinline__ void cpasync16(uint32_t dst, const void* src, int srcsize) {
    asm volatile("cp.async.cg.shared.global [%0], [%1], 16, %2;"
                 :: "r"(dst), "l"(src), "r"(srcsize));
}
__device__ __forceinline__ void cpcommit() {
    asm volatile("cp.async.commit_group;");
}
__device__ __forceinline__ void ldm4(uint32_t* r, uint32_t addr) {
    asm volatile("ldmatrix.sync.aligned.m8n8.x4.shared.b16 {%0,%1,%2,%3}, [%4];"
                 : "=r"(r[0]), "=r"(r[1]), "=r"(r[2]), "=r"(r[3]) : "r"(addr));
}
__device__ __forceinline__ void mma16816(float* d, const uint32_t* a, const uint32_t* b) {
    asm volatile(
        "mma.sync.aligned.m16n8k16.row.col.f32.f16.f16.f32 "
        "{%0,%1,%2,%3},{%4,%5,%6,%7},{%8,%9},{%0,%1,%2,%3};"
        : "+f"(d[0]), "+f"(d[1]), "+f"(d[2]), "+f"(d[3])
        : "r"(a[0]), "r"(a[1]), "r"(a[2]), "r"(a[3]), "r"(b[0]), "r"(b[1]));
}

// smem tile geometry: 128 rows x 64B (32 fp16), XOR swizzle, no padding.
#define TILE_B 8192
#define NSTAGE 3
#define STAGE_B (2 * TILE_B)         // X, W = 16 KB
#define X_OFF 0
#define W_OFF TILE_B

__device__ __forceinline__ uint32_t sw_off(int row, int bytecol) {
    const int ch = bytecol >> 4;
    return (uint32_t)(row * 64) + (((uint32_t)(ch ^ ((row >> 1) & 3))) << 4);
}

// ---------------- HMMA gathered multi-tap GEMM (pure fp16, fp32 acc) ---------
template <bool GATHER>
__global__ __launch_bounds__(256, 2)
void mma_conv_kernel(const __half* __restrict__ X,
                     const int* __restrict__ nbr,
                     const __half* __restrict__ W,
                     float* __restrict__ Y, int ntaps, int xk, int cptsh,
                     int pslot) {
    extern __shared__ char smem[];
    const uint32_t sb = smem_u32(smem);
    const int tid = threadIdx.x;
    const int wid = tid >> 5;
    const int lid = tid & 31;
    const int row0 = blockIdx.x * 128;
    const int kmask = (1 << cptsh) - 1;
    const int nsub = ntaps << cptsh;

    const int wm = (wid & 1) * 64;      // warp M offset
    const int wn = (wid >> 1) * 32;     // warp N offset

    const int lr = tid >> 1;            // load row 0..127
    const int lc = (tid & 1) * 2;       // chunk pair 0/2

    float acc[4][4][4];
#pragma unroll
    for (int i = 0; i < 4; i++)
#pragma unroll
        for (int j = 0; j < 4; j++)
#pragma unroll
            for (int q = 0; q < 4; q++) acc[i][j][q] = 0.f;

    auto src_of = [&](int s) -> int {
        const int grow = row0 + lr;
        if (!GATHER) return grow;
        const int tap = s >> cptsh;
        return (grow < NROWS) ? __ldg(nbr + (size_t)tap * NROWS + grow) : NROWS;
    };

    auto load_stage = [&](int s, int src) {
        const int buf = s % NSTAGE;
        const int kc = s & kmask;
        const uint32_t st = sb + buf * STAGE_B;
        const bool val = (unsigned)src < (unsigned)NROWS;
        const int srow = val ? src : 0;
        const int sz = val ? 16 : 0;
        const __half* xp = X + (size_t)srow * xk + kc * 32;
        const int tap = s >> cptsh;
        const __half* wp = W + ((size_t)tap * 128 + lr) * xk + kc * 32;
        const int sel = (lr >> 1) & 3;
        const uint32_t rbase = st + lr * 64;
#pragma unroll
        for (int c = 0; c < 2; c++) {
            const uint32_t d = rbase + (((uint32_t)((lc + c) ^ sel)) << 4);
            cpasync16(d + X_OFF, xp + (lc + c) * 8, sz);
            cpasync16(d + W_OFF, wp + (lc + c) * 8, 16);
        }
    };

    // ---- prologue: 2 stages in flight
    {
        int s0 = src_of(0);
        load_stage(0, s0);
        cpcommit();
    }
    if (nsub > 1) {
        int s1 = src_of(1);
        load_stage(1, s1);
        cpcommit();
    }
    int src2 = (nsub > 2) ? src_of(2) : 0;

    // ---- precomputed fragment smem offsets (swizzle hoisted out of mainloop)
    const int b_nrow = (lid & 7) + ((lid >> 4) << 3);
    const int b_kof = ((lid >> 3) & 1) * 16;
    const int a_row = lid & 15;
    const int a_kof = (lid >> 4) * 16;
    uint32_t boff[2][2], aoff[2][4];
#pragma unroll
    for (int kh = 0; kh < 2; kh++) {
#pragma unroll
        for (int half = 0; half < 2; half++)
            boff[kh][half] = W_OFF + sw_off(wn + half * 16 + b_nrow, kh * 32 + b_kof);
#pragma unroll
        for (int mi = 0; mi < 4; mi++)
            aoff[kh][mi] = X_OFF + sw_off(wm + mi * 16 + a_row, kh * 32 + a_kof);
    }

    for (int s = 0; s < nsub; s++) {
        if (s + 2 < nsub) {
            load_stage(s + 2, src2);
            cpcommit();
            src2 = src_of(s + 3);   // prefetch gather index 3 stages ahead
            asm volatile("cp.async.wait_group 2;");
        } else if (s + 1 < nsub) {
            asm volatile("cp.async.wait_group 1;");
        } else {
            asm volatile("cp.async.wait_group 0;");
        }
        __syncthreads();

        const uint32_t st = sb + (s % NSTAGE) * STAGE_B;
#pragma unroll
        for (int kh = 0; kh < 2; kh++) {
            uint32_t bh[4][2];
#pragma unroll
            for (int half = 0; half < 2; half++) {
                const uint32_t wa = st + boff[kh][half];
                uint32_t rg[4];
                ldm4(rg, wa);
                bh[half * 2][0] = rg[0]; bh[half * 2][1] = rg[1];
                bh[half * 2 + 1][0] = rg[2]; bh[half * 2 + 1][1] = rg[3];
            }
#pragma unroll
            for (int mi = 0; mi < 4; mi++) {
                const uint32_t aa = st + aoff[kh][mi];
                uint32_t ah[4];
                ldm4(ah, aa);
#pragma unroll
                for (int ni = 0; ni < 4; ni++)
                    mma16816(acc[mi][ni], ah, bh[ni]);
            }
        }
        __syncthreads();
    }

    // ---- epilogue 1: write fp32 tile
#pragma unroll
    for (int mi = 0; mi < 4; mi++) {
        const int m0 = row0 + wm + mi * 16 + (lid >> 2);
#pragma unroll
        for (int ni = 0; ni < 4; ni++) {
            const int col = wn + ni * 8 + 2 * (lid & 3);
            if (m0 < NROWS)
                *(float2*)(Y + (size_t)m0 * 128 + col) =
                    make_float2(acc[mi][ni][0], acc[mi][ni][1]);
            if (m0 + 8 < NROWS)
                *(float2*)(Y + (size_t)(m0 + 8) * 128 + col) =
                    make_float2(acc[mi][ni][2], acc[mi][ni][3]);
        }
    }

    // ---- epilogue 2: fused column stats (rows beyond NROWS contribute 0)
    float ts[8], tq[8];
#pragma unroll
    for (int ni = 0; ni < 4; ni++)
#pragma unroll
        for (int j = 0; j < 2; j++) {
            float s = 0.f, q = 0.f;
#pragma unroll
            for (int mi = 0; mi < 4; mi++) {
                float v0 = acc[mi][ni][j];
                float v1 = acc[mi][ni][j + 2];
                s += v0 + v1;
                q += v0 * v0 + v1 * v1;
            }
            ts[ni * 2 + j] = s;
            tq[ni * 2 + j] = q;
        }
#pragma unroll
    for (int o = 16; o >= 4; o >>= 1)
#pragma unroll
        for (int i = 0; i < 8; i++) {
            ts[i] += __shfl_down_sync(0xffffffffu, ts[i], o);
            tq[i] += __shfl_down_sync(0xffffffffu, tq[i], o);
        }
    __syncthreads();   // stage smem free for reuse
    float* ss = (float*)smem;          // [8][32]
    float* sq = ss + 256;
    if (lid < 4) {
#pragma unroll
        for (int ni = 0; ni < 4; ni++)
#pragma unroll
            for (int j = 0; j < 2; j++) {
                const int cl = ni * 8 + 2 * lid + j;
                ss[wid * 32 + cl] = ts[ni * 2 + j];
                sq[wid * 32 + cl] = tq[ni * 2 + j];
            }
    }
    __syncthreads();
    if (tid < COUT) {
        const int w0 = (tid >> 5) * 2;
        const int c = tid & 31;
        g_psum[pslot][blockIdx.x][tid] = ss[w0 * 32 + c] + ss[w0 * 32 + 32 + c];
        g_psq[pslot][blockIdx.x][tid]  = sq[w0 * 32 + c] + sq[w0 * 32 + 32 + c];
    }
}

// ---------------- prep: W transpose + fp16 convert ----------------------------
__global__ void wconv_kernel(const float* __restrict__ W,
                             __half* __restrict__ hi, int taps, int K) {
    int i = blockIdx.x * blockDim.x + threadIdx.x;
    int total = taps * 128 * K;
    if (i >= total) return;
    int kk = i % K;
    int t2 = i / K;
    int n = t2 & 127;
    int tap = t2 >> 7;
    float v = __ldg(W + ((size_t)tap * K + kk) * 128 + n);
    hi[i] = __float2half_rn(v);
}

// ---------------- prep: feats fp16 convert (vector) ---------------------------
__global__ void xconv_kernel(const float4* __restrict__ X,
                             uint2* __restrict__ hi, long long n4) {
    long long i = (long long)blockIdx.x * blockDim.x + threadIdx.x;
    if (i >= n4) return;
    float4 v = X[i];
    __half2 h01 = __halves2half2(__float2half_rn(v.x), __float2half_rn(v.y));
    __half2 h23 = __halves2half2(__float2half_rn(v.z), __float2half_rn(v.w));
    hi[i] = make_uint2(*(uint32_t*)&h01, *(uint32_t*)&h23);
}

// ---------------- BN finalize from fused partials (parallel) ------------------
__global__ void finalize_kernel(const float* __restrict__ g,
                                const float* __restrict__ b, int slot, int pslot) {
    __shared__ float ss[8][COUT];
    __shared__ float sq[8][COUT];
    const int col = threadIdx.x & (COUT - 1);
    const int chunk = threadIdx.x >> 7;     // 0..7
    const int beg = chunk * 196;
    const int end = (chunk == 7) ? NPART : (beg + 196);
    float s0 = 0.f, s1 = 0.f, q0 = 0.f, q1 = 0.f;
    int i = beg;
    for (; i + 1 < end; i += 2) {
        s0 += g_psum[pslot][i][col];
        q0 += g_psq[pslot][i][col];
        s1 += g_psum[pslot][i + 1][col];
        q1 += g_psq[pslot][i + 1][col];
    }
    for (; i < end; i++) {
        s0 += g_psum[pslot][i][col];
        q0 += g_psq[pslot][i][col];
    }
    ss[chunk][col] = s0 + s1;
    sq[chunk][col] = q0 + q1;
    __syncthreads();
    if (chunk == 0) {
        float s = 0.f, q = 0.f;
#pragma unroll
        for (int c = 0; c < 8; c++) { s += ss[c][col]; q += sq[c][col]; }
        float mean = s * (1.0f / NROWS);
        float var = q * (1.0f / NROWS) - mean * mean;
        float inv = g[col] * rsqrtf(var + EPSBN);
        g_inv[slot][col] = inv;
        g_shift[slot][col] = b[col] - mean * inv;
    }
}

// ---------------- BN apply (slot 0) fused with fp16 convert -------------------
__global__ void bnconv_kernel(const float4* __restrict__ X,
                              uint2* __restrict__ hi) {
    long long i = (long long)blockIdx.x * blockDim.x + threadIdx.x;
    const long long total = (long long)NROWS * COUT / 4;
    if (i >= total) return;
    int c4 = (int)(i & (COUT / 4 - 1)) * 4;
    float4 v = X[i];
    v.x = v.x * g_inv[0][c4 + 0] + g_shift[0][c4 + 0];
    v.y = v.y * g_inv[0][c4 + 1] + g_shift[0][c4 + 1];
    v.z = v.z * g_inv[0][c4 + 2] + g_shift[0][c4 + 2];
    v.w = v.w * g_inv[0][c4 + 3] + g_shift[0][c4 + 3];
    __half2 h01 = __halves2half2(__float2half_rn(v.x), __float2half_rn(v.y));
    __half2 h23 = __halves2half2(__float2half_rn(v.z), __float2half_rn(v.w));
    hi[i] = make_uint2(*(uint32_t*)&h01, *(uint32_t*)&h23);
}

// ---------------- final: relu(bn(res) + bn(skip)) ----------------------------
__global__ void final_kernel(float4* __restrict__ out) {
    long long i = (long long)blockIdx.x * blockDim.x + threadIdx.x;
    const long long total = (long long)NROWS * COUT / 4;
    if (i >= total) return;
    int c4 = (int)(i & (COUT / 4 - 1)) * 4;
    const float4 r = ((const float4*)g_respre)[i];
    const float4 s = ((const float4*)g_skippre)[i];
    float4 o;
    o.x = fmaxf(r.x * g_inv[1][c4 + 0] + g_shift[1][c4 + 0] +
                s.x * g_inv[2][c4 + 0] + g_shift[2][c4 + 0], 0.f);
    o.y = fmaxf(r.y * g_inv[1][c4 + 1] + g_shift[1][c4 + 1] +
                s.y * g_inv[2][c4 + 1] + g_shift[2][c4 + 1], 0.f);
    o.z = fmaxf(r.z * g_inv[1][c4 + 2] + g_shift[1][c4 + 2] +
                s.z * g_inv[2][c4 + 2] + g_shift[2][c4 + 2], 0.f);
    o.w = fmaxf(r.w * g_inv[1][c4 + 3] + g_shift[1][c4 + 3] +
                s.w * g_inv[2][c4 + 3] + g_shift[2][c4 + 3], 0.f);
    out[i] = o;
}

// ---------------- launch ------------------------------------------------------
extern "C" void kernel_launch(void* const* d_in, const int* in_sizes, int n_in,
                              void* d_out, int out_size) {
    const float* feats = (const float*)d_in[0];
    const int*   nbr   = (const int*)d_in[1];
    const float* W1    = (const float*)d_in[2];
    const float* g1    = (const float*)d_in[3];
    const float* b1    = (const float*)d_in[4];
    const float* W2    = (const float*)d_in[5];
    const float* g2    = (const float*)d_in[6];
    const float* b2    = (const float*)d_in[7];
    const float* Wsk   = (const float*)d_in[8];
    const float* gsk   = (const float*)d_in[9];
    const float* bsk   = (const float*)d_in[10];
    float* out = (float*)d_out;

    float *hpre, *respre, *skippre;
    __half *fh, *hh, *w1h, *w2h, *wskh;
    cudaGetSymbolAddress((void**)&hpre, g_hpre);
    cudaGetSymbolAddress((void**)&respre, g_respre);
    cudaGetSymbolAddress((void**)&skippre, g_skippre);
    cudaGetSymbolAddress((void**)&fh, g_fh);
    cudaGetSymbolAddress((void**)&hh, g_hh);
    cudaGetSymbolAddress((void**)&w1h, g_w1h);
    cudaGetSymbolAddress((void**)&w2h, g_w2h);
    cudaGetSymbolAddress((void**)&wskh, g_wskh);

    const int SMEM_BYTES = NSTAGE * STAGE_B;  // 49152
    cudaFuncSetAttribute(mma_conv_kernel<true>,
                         cudaFuncAttributeMaxDynamicSharedMemorySize, SMEM_BYTES);
    cudaFuncSetAttribute(mma_conv_kernel<false>,
                         cudaFuncAttributeMaxDynamicSharedMemorySize, SMEM_BYTES);

    const int grid = NPART;  // 1563
    const long long total4 = (long long)NROWS * COUT / 4;
    const int egrid = (int)((total4 + 255) / 256);
    const long long f4 = (long long)NROWS * CIN1 / 4;

    // ---- prep (ordered so launch index 3 == conv1, which ncu captures)
    wconv_kernel<<<(NTAPS * 128 * CIN1 + 255) / 256, 256>>>(W1, w1h, NTAPS, CIN1);
    xconv_kernel<<<(int)((f4 + 255) / 256), 256>>>((const float4*)feats,
                                                   (uint2*)fh, f4);
    wconv_kernel<<<(NTAPS * 128 * COUT + 255) / 256, 256>>>(W2, w2h, NTAPS, COUT);

    // ---- conv1: 27 taps, K=64  (launch index 3 -> profiled); stats -> pslot 0
    mma_conv_kernel<true><<<grid, 256, SMEM_BYTES>>>(fh, nbr, w1h, hpre,
                                                     NTAPS, CIN1, 1, 0);

    // ---- skip branch; stats -> pslot 1
    wconv_kernel<<<(128 * CIN1 + 255) / 256, 256>>>(Wsk, wskh, 1, CIN1);
    mma_conv_kernel<false><<<grid, 256, SMEM_BYTES>>>(fh, nullptr, wskh, skippre,
                                                      1, CIN1, 1, 1);

    // ---- BN1 finalize (parallel) + fused apply+convert
    finalize_kernel<<<1, 1024>>>(g1, b1, 0, 0);
    bnconv_kernel<<<egrid, 256>>>((const float4*)hpre, (uint2*)hh);
    // ---- conv2: 27 taps, K=128; stats -> pslot 0
    mma_conv_kernel<true><<<grid, 256, SMEM_BYTES>>>(hh, nbr, w2h, respre,
                                                     NTAPS, COUT, 2, 0);
    // ---- BN2 + BNskip finalize
    finalize_kernel<<<1, 1024>>>(g2, b2, 1, 0);
    finalize_kernel<<<1, 1024>>>(gsk, bsk, 2, 1);
    // ---- out = relu(bn(res) + bn(skip))
    final_kernel<<<egrid, 256>>>((float4*)out);
}

// round 14
// speedup vs baseline: 2.5928x; 1.0298x over previous
#include <cuda_runtime.h>
#include <cuda_fp16.h>
#include <cstdint>

#define NROWS 200000
#define CIN1  64
#define COUT  128
#define NTAPS 27
#define EPSBN 1e-5f
#define NPART 1563   // ceil(NROWS/128) == conv grid size

// ---------------- scratch (device globals; no allocation allowed) ----------
__device__ float g_hpre[(size_t)NROWS * COUT];    // conv1 pre-BN
__device__ float g_respre[(size_t)NROWS * COUT];  // conv2 pre-BN
__device__ float g_skippre[(size_t)NROWS * COUT]; // skip pre-BN
__device__ __half g_fh[(size_t)NROWS * CIN1];
__device__ __half g_hh[(size_t)NROWS * COUT];
__device__ __half g_w1h[(size_t)NTAPS * COUT * CIN1];  // [tap][n][k]
__device__ __half g_w2h[(size_t)NTAPS * COUT * COUT];
__device__ __half g_wskh[(size_t)COUT * CIN1];
__device__ float g_psum[2][NPART][COUT];   // fused per-CTA stats partials
__device__ float g_psq[2][NPART][COUT];
__device__ float g_inv[3][COUT];    // g * rsqrt(var+eps)
__device__ float g_shift[3][COUT];  // b - mean*inv

// ---------------- PTX helpers (baseline features only) -----------------------
__device__ __forceinline__ uint32_t smem_u32(const void* p) {
    uint32_t a;
    asm("{ .reg .u64 t; cvta.to.shared.u64 t, %1; cvt.u32.u64 %0, t; }"
        : "=r"(a) : "l"(p));
    return a;
}
__device__ __forceinline__ void cpasync16(uint32_t dst, const void* src, int srcsize) {
    asm volatile("cp.async.cg.shared.global [%0], [%1], 16, %2;"
                 :: "r"(dst), "l"(src), "r"(srcsize));
}
__device__ __forceinline__ void cpcommit() {
    asm volatile("cp.async.commit_group;");
}
__device__ __forceinline__ void ldm4(uint32_t* r, uint32_t addr) {
    asm volatile("ldmatrix.sync.aligned.m8n8.x4.shared.b16 {%0,%1,%2,%3}, [%4];"
                 : "=r"(r[0]), "=r"(r[1]), "=r"(r[2]), "=r"(r[3]) : "r"(addr));
}
__device__ __forceinline__ void mma16816(float* d, const uint32_t* a, const uint32_t* b) {
    asm volatile(
        "mma.sync.aligned.m16n8k16.row.col.f32.f16.f16.f32 "
        "{%0,%1,%2,%3},{%4,%5,%6,%7},{%8,%9},{%0,%1,%2,%3};"
        : "+f"(d[0]), "+f"(d[1]), "+f"(d[2]), "+f"(d[3])
        : "r"(a[0]), "r"(a[1]), "r"(a[2]), "r"(a[3]), "r"(b[0]), "r"(b[1]));
}

// smem tile geometry: 128 rows x 64B (32 fp16), XOR swizzle, no padding.
#define TILE_B 8192
#define NSTAGE 4
#define STAGE_B (2 * TILE_B)         // X, W = 16 KB
#define X_OFF 0
#define W_OFF TILE_B

__device__ __forceinline__ uint32_t sw_off(int row, int bytecol) {
    const int ch = bytecol >> 4;
    return (uint32_t)(row * 64) + (((uint32_t)(ch ^ ((row >> 1) & 3))) << 4);
}

// ---------------- HMMA gathered multi-tap GEMM (pure fp16, fp32 acc) ---------
// Pipeline: wait(s) -> barrier -> issue loads(s+3) -> compute(s).
// Single barrier per stage: after barrier s all warps finished compute s-1,
// so overwriting buffer (s+3)%4 == (s-1)%4 is race-free.
template <bool GATHER>
__global__ __launch_bounds__(256, 2)
void mma_conv_kernel(const __half* __restrict__ X,
                     const int* __restrict__ nbr,
                     const __half* __restrict__ W,
                     float* __restrict__ Y, int ntaps, int xk, int cptsh,
                     int pslot) {
    extern __shared__ char smem[];
    const uint32_t sb = smem_u32(smem);
    const int tid = threadIdx.x;
    const int wid = tid >> 5;
    const int lid = tid & 31;
    const int row0 = blockIdx.x * 128;
    const int kmask = (1 << cptsh) - 1;
    const int nsub = ntaps << cptsh;

    const int wm = (wid & 1) * 64;      // warp M offset
    const int wn = (wid >> 1) * 32;     // warp N offset

    const int lr = tid >> 1;            // load row 0..127
    const int lc = (tid & 1) * 2;       // chunk pair 0/2

    float acc[4][4][4];
#pragma unroll
    for (int i = 0; i < 4; i++)
#pragma unroll
        for (int j = 0; j < 4; j++)
#pragma unroll
            for (int q = 0; q < 4; q++) acc[i][j][q] = 0.f;

    auto src_of = [&](int s) -> int {
        const int grow = row0 + lr;
        if (!GATHER) return grow;
        const int tap = s >> cptsh;
        return (grow < NROWS) ? __ldg(nbr + (size_t)tap * NROWS + grow) : NROWS;
    };

    auto load_stage = [&](int s, int src) {
        const int buf = s & (NSTAGE - 1);
        const int kc = s & kmask;
        const uint32_t st = sb + buf * STAGE_B;
        const bool val = (unsigned)src < (unsigned)NROWS;
        const int srow = val ? src : 0;
        const int sz = val ? 16 : 0;
        const __half* xp = X + (size_t)srow * xk + kc * 32;
        const int tap = s >> cptsh;
        const __half* wp = W + ((size_t)tap * 128 + lr) * xk + kc * 32;
        const int sel = (lr >> 1) & 3;
        const uint32_t rbase = st + lr * 64;
#pragma unroll
        for (int c = 0; c < 2; c++) {
            const uint32_t d = rbase + (((uint32_t)((lc + c) ^ sel)) << 4);
            cpasync16(d + X_OFF, xp + (lc + c) * 8, sz);
            cpasync16(d + W_OFF, wp + (lc + c) * 8, 16);
        }
    };

    // ---- prologue: up to 3 stages in flight
    load_stage(0, src_of(0));
    cpcommit();
    if (nsub > 1) { load_stage(1, src_of(1)); cpcommit(); }
    if (nsub > 2) { load_stage(2, src_of(2)); cpcommit(); }
    int src3 = (nsub > 3) ? src_of(3) : 0;

    // ---- precomputed fragment smem offsets (swizzle hoisted out of mainloop)
    const int b_nrow = (lid & 7) + ((lid >> 4) << 3);
    const int b_kof = ((lid >> 3) & 1) * 16;
    const int a_row = lid & 15;
    const int a_kof = (lid >> 4) * 16;
    uint32_t boff[2][2], aoff[2][4];
#pragma unroll
    for (int kh = 0; kh < 2; kh++) {
#pragma unroll
        for (int half = 0; half < 2; half++)
            boff[kh][half] = W_OFF + sw_off(wn + half * 16 + b_nrow, kh * 32 + b_kof);
#pragma unroll
        for (int mi = 0; mi < 4; mi++)
            aoff[kh][mi] = X_OFF + sw_off(wm + mi * 16 + a_row, kh * 32 + a_kof);
    }

    for (int s = 0; s < nsub; s++) {
        // wait for stage s data (groups beyond s may remain outstanding)
        if (s + 2 < nsub) {
            asm volatile("cp.async.wait_group 2;");
        } else if (s + 1 < nsub) {
            asm volatile("cp.async.wait_group 1;");
        } else {
            asm volatile("cp.async.wait_group 0;");
        }
        __syncthreads();   // single barrier per stage

        // issue next loads AFTER barrier (buffer (s+3)%4 is free now)
        if (s + 3 < nsub) {
            load_stage(s + 3, src3);
            cpcommit();
            src3 = (s + 4 < nsub) ? src_of(s + 4) : 0;
        }

        const uint32_t st = sb + (s & (NSTAGE - 1)) * STAGE_B;
#pragma unroll
        for (int kh = 0; kh < 2; kh++) {
            uint32_t bh[4][2];
#pragma unroll
            for (int half = 0; half < 2; half++) {
                const uint32_t wa = st + boff[kh][half];
                uint32_t rg[4];
                ldm4(rg, wa);
                bh[half * 2][0] = rg[0]; bh[half * 2][1] = rg[1];
                bh[half * 2 + 1][0] = rg[2]; bh[half * 2 + 1][1] = rg[3];
            }
#pragma unroll
            for (int mi = 0; mi < 4; mi++) {
                const uint32_t aa = st + aoff[kh][mi];
                uint32_t ah[4];
                ldm4(ah, aa);
#pragma unroll
                for (int ni = 0; ni < 4; ni++)
                    mma16816(acc[mi][ni], ah, bh[ni]);
            }
        }
    }

    // ---- epilogue 1: write fp32 tile
#pragma unroll
    for (int mi = 0; mi < 4; mi++) {
        const int m0 = row0 + wm + mi * 16 + (lid >> 2);
#pragma unroll
        for (int ni = 0; ni < 4; ni++) {
            const int col = wn + ni * 8 + 2 * (lid & 3);
            if (m0 < NROWS)
                *(float2*)(Y + (size_t)m0 * 128 + col) =
                    make_float2(acc[mi][ni][0], acc[mi][ni][1]);
            if (m0 + 8 < NROWS)
                *(float2*)(Y + (size_t)(m0 + 8) * 128 + col) =
                    make_float2(acc[mi][ni][2], acc[mi][ni][3]);
        }
    }

    // ---- epilogue 2: fused column stats (rows beyond NROWS contribute 0)
    float ts[8], tq[8];
#pragma unroll
    for (int ni = 0; ni < 4; ni++)
#pragma unroll
        for (int j = 0; j < 2; j++) {
            float s = 0.f, q = 0.f;
#pragma unroll
            for (int mi = 0; mi < 4; mi++) {
                float v0 = acc[mi][ni][j];
                float v1 = acc[mi][ni][j + 2];
                s += v0 + v1;
                q += v0 * v0 + v1 * v1;
            }
            ts[ni * 2 + j] = s;
            tq[ni * 2 + j] = q;
        }
#pragma unroll
    for (int o = 16; o >= 4; o >>= 1)
#pragma unroll
        for (int i = 0; i < 8; i++) {
            ts[i] += __shfl_down_sync(0xffffffffu, ts[i], o);
            tq[i] += __shfl_down_sync(0xffffffffu, tq[i], o);
        }
    __syncthreads();   // all compute done; stage smem free for reuse
    float* ss = (float*)smem;          // [8][32]
    float* sq = ss + 256;
    if (lid < 4) {
#pragma unroll
        for (int ni = 0; ni < 4; ni++)
#pragma unroll
            for (int j = 0; j < 2; j++) {
                const int cl = ni * 8 + 2 * lid + j;
                ss[wid * 32 + cl] = ts[ni * 2 + j];
                sq[wid * 32 + cl] = tq[ni * 2 + j];
            }
    }
    __syncthreads();
    if (tid < COUT) {
        const int w0 = (tid >> 5) * 2;
        const int c = tid & 31;
        g_psum[pslot][blockIdx.x][tid] = ss[w0 * 32 + c] + ss[w0 * 32 + 32 + c];
        g_psq[pslot][blockIdx.x][tid]  = sq[w0 * 32 + c] + sq[w0 * 32 + 32 + c];
    }
}

// ---------------- prep: W transpose + fp16 convert ----------------------------
__global__ void wconv_kernel(const float* __restrict__ W,
                             __half* __restrict__ hi, int taps, int K) {
    int i = blockIdx.x * blockDim.x + threadIdx.x;
    int total = taps * 128 * K;
    if (i >= total) return;
    int kk = i % K;
    int t2 = i / K;
    int n = t2 & 127;
    int tap = t2 >> 7;
    float v = __ldg(W + ((size_t)tap * K + kk) * 128 + n);
    hi[i] = __float2half_rn(v);
}

// ---------------- prep: feats fp16 convert (vector) ---------------------------
__global__ void xconv_kernel(const float4* __restrict__ X,
                             uint2* __restrict__ hi, long long n4) {
    long long i = (long long)blockIdx.x * blockDim.x + threadIdx.x;
    if (i >= n4) return;
    float4 v = X[i];
    __half2 h01 = __halves2half2(__float2half_rn(v.x), __float2half_rn(v.y));
    __half2 h23 = __halves2half2(__float2half_rn(v.z), __float2half_rn(v.w));
    hi[i] = make_uint2(*(uint32_t*)&h01, *(uint32_t*)&h23);
}

// ---------------- BN finalize from fused partials (parallel) ------------------
__device__ __forceinline__ void finalize_body(const float* g, const float* b,
                                              int slot, int pslot) {
    __shared__ float ss[8][COUT];
    __shared__ float sq[8][COUT];
    const int col = threadIdx.x & (COUT - 1);
    const int chunk = threadIdx.x >> 7;     // 0..7
    const int beg = chunk * 196;
    const int end = (chunk == 7) ? NPART : (beg + 196);
    float s0 = 0.f, s1 = 0.f, q0 = 0.f, q1 = 0.f;
    int i = beg;
    for (; i + 1 < end; i += 2) {
        s0 += g_psum[pslot][i][col];
        q0 += g_psq[pslot][i][col];
        s1 += g_psum[pslot][i + 1][col];
        q1 += g_psq[pslot][i + 1][col];
    }
    for (; i < end; i++) {
        s0 += g_psum[pslot][i][col];
        q0 += g_psq[pslot][i][col];
    }
    ss[chunk][col] = s0 + s1;
    sq[chunk][col] = q0 + q1;
    __syncthreads();
    if (chunk == 0) {
        float s = 0.f, q = 0.f;
#pragma unroll
        for (int c = 0; c < 8; c++) { s += ss[c][col]; q += sq[c][col]; }
        float mean = s * (1.0f / NROWS);
        float var = q * (1.0f / NROWS) - mean * mean;
        float inv = g[col] * rsqrtf(var + EPSBN);
        g_inv[slot][col] = inv;
        g_shift[slot][col] = b[col] - mean * inv;
    }
}

__global__ void finalize_kernel(const float* __restrict__ g,
                                const float* __restrict__ b, int slot, int pslot) {
    finalize_body(g, b, slot, pslot);
}

// fused: block 0 -> BN2 (slot 1, pslot 0); block 1 -> BNskip (slot 2, pslot 1)
__global__ void finalize2_kernel(const float* __restrict__ g2,
                                 const float* __restrict__ b2,
                                 const float* __restrict__ gsk,
                                 const float* __restrict__ bsk) {
    if (blockIdx.x == 0) finalize_body(g2, b2, 1, 0);
    else                 finalize_body(gsk, bsk, 2, 1);
}

// ---------------- BN apply (slot 0) fused with fp16 convert -------------------
__global__ void bnconv_kernel(const float4* __restrict__ X,
                              uint2* __restrict__ hi) {
    long long i = (long long)blockIdx.x * blockDim.x + threadIdx.x;
    const long long total = (long long)NROWS * COUT / 4;
    if (i >= total) return;
    int c4 = (int)(i & (COUT / 4 - 1)) * 4;
    float4 v = X[i];
    v.x = v.x * g_inv[0][c4 + 0] + g_shift[0][c4 + 0];
    v.y = v.y * g_inv[0][c4 + 1] + g_shift[0][c4 + 1];
    v.z = v.z * g_inv[0][c4 + 2] + g_shift[0][c4 + 2];
    v.w = v.w * g_inv[0][c4 + 3] + g_shift[0][c4 + 3];
    __half2 h01 = __halves2half2(__float2half_rn(v.x), __float2half_rn(v.y));
    __half2 h23 = __halves2half2(__float2half_rn(v.z), __float2half_rn(v.w));
    hi[i] = make_uint2(*(uint32_t*)&h01, *(uint32_t*)&h23);
}

// ---------------- final: relu(bn(res) + bn(skip)) ----------------------------
__global__ void final_kernel(float4* __restrict__ out) {
    long long i = (long long)blockIdx.x * blockDim.x + threadIdx.x;
    const long long total = (long long)NROWS * COUT / 4;
    if (i >= total) return;
    int c4 = (int)(i & (COUT / 4 - 1)) * 4;
    const float4 r = ((const float4*)g_respre)[i];
    const float4 s = ((const float4*)g_skippre)[i];
    float4 o;
    o.x = fmaxf(r.x * g_inv[1][c4 + 0] + g_shift[1][c4 + 0] +
                s.x * g_inv[2][c4 + 0] + g_shift[2][c4 + 0], 0.f);
    o.y = fmaxf(r.y * g_inv[1][c4 + 1] + g_shift[1][c4 + 1] +
                s.y * g_inv[2][c4 + 1] + g_shift[2][c4 + 1], 0.f);
    o.z = fmaxf(r.z * g_inv[1][c4 + 2] + g_shift[1][c4 + 2] +
                s.z * g_inv[2][c4 + 2] + g_shift[2][c4 + 2], 0.f);
    o.w = fmaxf(r.w * g_inv[1][c4 + 3] + g_shift[1][c4 + 3] +
                s.w * g_inv[2][c4 + 3] + g_shift[2][c4 + 3], 0.f);
    out[i] = o;
}

// ---------------- launch ------------------------------------------------------
extern "C" void kernel_launch(void* const* d_in, const int* in_sizes, int n_in,
                              void* d_out, int out_size) {
    const float* feats = (const float*)d_in[0];
    const int*   nbr   = (const int*)d_in[1];
    const float* W1    = (const float*)d_in[2];
    const float* g1    = (const float*)d_in[3];
    const float* b1    = (const float*)d_in[4];
    const float* W2    = (const float*)d_in[5];
    const float* g2    = (const float*)d_in[6];
    const float* b2    = (const float*)d_in[7];
    const float* Wsk   = (const float*)d_in[8];
    const float* gsk   = (const float*)d_in[9];
    const float* bsk   = (const float*)d_in[10];
    float* out = (float*)d_out;

    float *hpre, *respre, *skippre;
    __half *fh, *hh, *w1h, *w2h, *wskh;
    cudaGetSymbolAddress((void**)&hpre, g_hpre);
    cudaGetSymbolAddress((void**)&respre, g_respre);
    cudaGetSymbolAddress((void**)&skippre, g_skippre);
    cudaGetSymbolAddress((void**)&fh, g_fh);
    cudaGetSymbolAddress((void**)&hh, g_hh);
    cudaGetSymbolAddress((void**)&w1h, g_w1h);
    cudaGetSymbolAddress((void**)&w2h, g_w2h);
    cudaGetSymbolAddress((void**)&wskh, g_wskh);

    const int SMEM_BYTES = NSTAGE * STAGE_B;  // 65536
    cudaFuncSetAttribute(mma_conv_kernel<true>,
                         cudaFuncAttributeMaxDynamicSharedMemorySize, SMEM_BYTES);
    cudaFuncSetAttribute(mma_conv_kernel<false>,
                         cudaFuncAttributeMaxDynamicSharedMemorySize, SMEM_BYTES);

    const int grid = NPART;  // 1563
    const long long total4 = (long long)NROWS * COUT / 4;
    const int egrid = (int)((total4 + 255) / 256);
    const long long f4 = (long long)NROWS * CIN1 / 4;

    // ---- prep (ordered so launch index 3 == conv1, which ncu captures)
    wconv_kernel<<<(NTAPS * 128 * CIN1 + 255) / 256, 256>>>(W1, w1h, NTAPS, CIN1);
    xconv_kernel<<<(int)((f4 + 255) / 256), 256>>>((const float4*)feats,
                                                   (uint2*)fh, f4);
    wconv_kernel<<<(NTAPS * 128 * COUT + 255) / 256, 256>>>(W2, w2h, NTAPS, COUT);

    // ---- conv1: 27 taps, K=64  (launch index 3 -> profiled); stats -> pslot 0
    mma_conv_kernel<true><<<grid, 256, SMEM_BYTES>>>(fh, nbr, w1h, hpre,
                                                     NTAPS, CIN1, 1, 0);

    // ---- skip branch; stats -> pslot 1
    wconv_kernel<<<(128 * CIN1 + 255) / 256, 256>>>(Wsk, wskh, 1, CIN1);
    mma_conv_kernel<false><<<grid, 256, SMEM_BYTES>>>(fh, nullptr, wskh, skippre,
                                                      1, CIN1, 1, 1);

    // ---- BN1 finalize (parallel) + fused apply+convert
    finalize_kernel<<<1, 1024>>>(g1, b1, 0, 0);
    bnconv_kernel<<<egrid, 256>>>((const float4*)hpre, (uint2*)hh);
    // ---- conv2: 27 taps, K=128; stats -> pslot 0
    mma_conv_kernel<true><<<grid, 256, SMEM_BYTES>>>(hh, nbr, w2h, respre,
                                                     NTAPS, COUT, 2, 0);
    // ---- BN2 + BNskip finalize (fused into one launch)
    finalize2_kernel<<<2, 1024>>>(g2, b2, gsk, bsk);
    // ---- out = relu(bn(res) + bn(skip))
    final_kernel<<<egrid, 256>>>((float4*)out);
}